// round 3
// baseline (speedup 1.0000x reference)
#include <cuda_runtime.h>
#include <math.h>

// Problem constants (B=1, CX=CY=CZ=32, QX=QY=QZ=48)
#define QTOT   110592      // 48^3
#define CTXC   96
#define NCOORD 60
#define NIN0   156         // CTXC + NCOORD
#define OUTC   45
#define PTS    8           // points per CTA
#define ROWS   64          // PTS * 8 corners
#define XSTR   97          // padded stride for 96-wide activation buffers
#define CSTR   61          // padded stride for coord features
#define THREADS 256

// Shared memory layout (in floats); all offsets multiple of 4 for float4 copies
#define OFF_X    0
#define OFF_HA   (ROWS*XSTR)            // 6208
#define OFF_HB   (2*ROWS*XSTR)          // 12416
#define OFF_C    (3*ROWS*XSTR)          // 18624
#define OFF_W    (OFF_C + ROWS*CSTR)    // 22528
#define OFF_B    (OFF_W + NIN0*CTXC)    // 37504
#define OFF_W8   (OFF_B + CTXC)         // 37600
#define OFF_PT   (OFF_W8 + ROWS)        // 37664  (t factors, 24)
#define OFF_PQ   (OFF_PT + 24)          // ptQ, 24
#define OFF_PR   (OFF_PQ + 24)          // raw rel000, 24
#define OFF_MISC (OFF_PR + 24)          // qv[3], vox[3], min[3]
#define OFF_INT  (OFF_MISC + 12)        // ints: near[24], rowBase[64]
#define SMEM_FLOATS (OFF_INT + 24 + 64)
#define SMEM_BYTES  (SMEM_FLOATS * 4)

__device__ unsigned int g_min_enc[3];

__device__ __forceinline__ unsigned fenc(float f) {
    unsigned u = __float_as_uint(f);
    return (u & 0x80000000u) ? ~u : (u | 0x80000000u);
}
__device__ __forceinline__ float fdec(unsigned e) {
    return __uint_as_float((e & 0x80000000u) ? (e ^ 0x80000000u) : ~e);
}
__device__ __forceinline__ float silu(float x) {
    return x * (1.0f / (1.0f + __expf(-x)));
}

__global__ void init_min_kernel() {
    if (threadIdx.x < 3) g_min_enc[threadIdx.x] = 0xFFFFFFFFu;
}

// Global min over raw rel000 (pre-clamp) per dim. Clamp is applied later (monotone).
__global__ void min_kernel(const float* __restrict__ ext, const float* __restrict__ qc) {
    int p = blockIdx.x * blockDim.x + threadIdx.x;
    float raw[3] = {1e30f, 1e30f, 1e30f};
    if (p < QTOT) {
        int ni[3];
        float q[3];
#pragma unroll
        for (int d = 0; d < 3; d++) {
            float o = ext[d * 32768];
            float v = fabsf(ext[d * 32768 + 1057] - o);
            q[d] = qc[d * QTOT + p];
            int n = __float2int_rn((q[d] - o) / v);
            ni[d] = min(max(n, 0), 30);
        }
#pragma unroll
        for (int d = 0; d < 3; d++) {
            float cc = ext[d * 32768 + ni[0] * 1024 + ni[1] * 32 + ni[2]];
            raw[d] = cc - q[d];
        }
    }
#pragma unroll
    for (int off = 16; off; off >>= 1) {
#pragma unroll
        for (int d = 0; d < 3; d++)
            raw[d] = fminf(raw[d], __shfl_down_sync(0xffffffffu, raw[d], off));
    }
    if ((threadIdx.x & 31) == 0) {
#pragma unroll
        for (int d = 0; d < 3; d++)
            atomicMin(&g_min_enc[d], fenc(raw[d]));
    }
}

// Register-tiled matvec accumulate: 4 rows x NT neurons per thread.
template <int NT>
__device__ __forceinline__ void mv_acc(const float* __restrict__ in, int istr, int n_in,
                                       const float* __restrict__ w, int wstr, int n0,
                                       int r0, float (&acc)[4][NT]) {
#pragma unroll 4
    for (int i = 0; i < n_in; ++i) {
        float a0 = in[(r0 + 0) * istr + i];
        float a1 = in[(r0 + 1) * istr + i];
        float a2 = in[(r0 + 2) * istr + i];
        float a3 = in[(r0 + 3) * istr + i];
        const float* wr = w + i * wstr + n0;
#pragma unroll
        for (int v = 0; v < NT; ++v) {
            float wv = wr[v];
            acc[0][v] = fmaf(a0, wv, acc[0][v]);
            acc[1][v] = fmaf(a1, wv, acc[1][v]);
            acc[2][v] = fmaf(a2, wv, acc[2][v]);
            acc[3][v] = fmaf(a3, wv, acc[3][v]);
        }
    }
}

__device__ __forceinline__ void loadW4(float* dst, const float* __restrict__ src, int n, int tid) {
    const float4* s4 = (const float4*)src;
    float4* d4 = (float4*)dst;
    for (int i = tid; i < (n >> 2); i += THREADS) d4[i] = s4[i];
}

__global__ __launch_bounds__(THREADS, 1) void main_kernel(
    const float* __restrict__ ctxv, const float* __restrict__ ext,
    const float* __restrict__ qvs, const float* __restrict__ qc,
    const float* __restrict__ w00, const float* __restrict__ b00,
    const float* __restrict__ w01, const float* __restrict__ b01,
    const float* __restrict__ w02, const float* __restrict__ b02,
    const float* __restrict__ w10, const float* __restrict__ b10,
    const float* __restrict__ w11, const float* __restrict__ b11,
    const float* __restrict__ w12, const float* __restrict__ b12,
    const float* __restrict__ pw, const float* __restrict__ pb,
    float* __restrict__ out) {
    extern __shared__ float sm[];
    float* xS = sm + OFF_X;
    float* hA = sm + OFF_HA;
    float* hB = sm + OFF_HB;
    float* coordS = sm + OFF_C;
    float* wS = sm + OFF_W;
    float* bS = sm + OFF_B;
    float* w8S = sm + OFF_W8;
    float* ptT = sm + OFF_PT;
    float* ptQ = sm + OFF_PQ;
    float* ptR = sm + OFF_PR;
    float* qvS = sm + OFF_MISC;
    float* voxS = qvS + 3;
    float* minS = voxS + 3;
    int* nearS = (int*)(sm + OFF_INT);
    int* rowBaseS = nearS + 24;

    const int tid = threadIdx.x;
    const int pbase = blockIdx.x * PTS;

    // ---- Region 1: per-dim constants + per-point nearest ----
    if (tid < 3) {
        float o = ext[tid * 32768];
        qvS[tid] = qvs[tid];
        voxS[tid] = fabsf(ext[tid * 32768 + 1057] - o);
        minS[tid] = fdec(g_min_enc[tid]);
    }
    if (tid < 24) {
        int pt = tid / 3, d = tid - pt * 3;
        float o = ext[d * 32768];
        float v = fabsf(ext[d * 32768 + 1057] - o);
        float q = qc[d * QTOT + pbase + pt];
        int n = __float2int_rn((q - o) / v);
        nearS[tid] = min(max(n, 0), 30);
        ptQ[tid] = q;
    }
    __syncthreads();

    // ---- Region 2: raw rel000, trilinear t, per-row gather base ----
    if (tid < 24) {
        int pt = tid / 3, d = tid - pt * 3;
        float cc = ext[d * 32768 + nearS[pt * 3] * 1024 + nearS[pt * 3 + 1] * 32 + nearS[pt * 3 + 2]];
        float raw = cc - ptQ[tid];
        ptR[tid] = raw;
        float v = voxS[d];
        float clampc = fmaf(v, -0.5f, 1e-7f);
        float rel0 = fmaxf(raw, clampc);
        float g = fminf(fmaxf((rel0 - 0.5f) * 2.0f, -1.0f + 1e-7f), 1.0f - 1e-7f);
        ptT[tid] = (g + 1.0f) * 0.5f;
    }
    if (tid < ROWS) {
        int pt = tid >> 3, cn = tid & 7;
        int ix = nearS[pt * 3 + 0] + ((cn >> 2) & 1);
        int iy = nearS[pt * 3 + 1] + ((cn >> 1) & 1);
        int iz = nearS[pt * 3 + 2] + (cn & 1);
        rowBaseS[tid] = ix * 1024 + iy * 32 + iz;
    }
    __syncthreads();

    // ---- Region 3: trilinear weights, coord features, context gather ----
    if (tid < ROWS) {
        int pt = tid >> 3, cn = tid & 7;
        // Reference mapping: corner i (dim0) uses t[dim2], j uses t[dim1], k uses t[dim0]
        float wi = ((cn >> 2) & 1) ? ptT[pt * 3 + 2] : 1.0f - ptT[pt * 3 + 2];
        float wj = ((cn >> 1) & 1) ? ptT[pt * 3 + 1] : 1.0f - ptT[pt * 3 + 1];
        float wk = (cn & 1) ? ptT[pt * 3 + 0] : 1.0f - ptT[pt * 3 + 0];
        w8S[tid] = wi * wj * wk;
    }
    if (tid < ROWS * 3) {
        int row = tid / 3, d = tid - row * 3;
        int pt = row >> 3, cn = row & 7;
        int off = (d == 0) ? ((cn >> 2) & 1) : (d == 1) ? ((cn >> 1) & 1) : (cn & 1);
        float v = voxS[d];
        float clampc = fmaf(v, -0.5f, 1e-7f);
        float raw = ptR[pt * 3 + d] + (float)off * v;
        float rel = fmaxf(raw, clampc);
        float rmin = fmaxf(minS[d] + (float)off * v, clampc);
        float rn = (rel - rmin) / (1.5f * v);
        float cc = ext[d * 32768 + rowBaseS[row]];
        float* cf = coordS + row * CSTR;
        cf[0 + d] = qvS[d];
        cf[3 + d] = cc;
        cf[6 + d] = ptQ[pt * 3 + d];
        cf[9 + d] = rn;
        const float TWO_PI = 6.2831853071795864769f;
#pragma unroll
        for (int f = 0; f < 8; ++f) {
            float fr = exp2f((float)f * 0.29024101186092026f);  // 5^(f/8)
            float ang = TWO_PI * rn * fr;
            cf[12 + d * 16 + f] = sinf(ang);
            cf[12 + d * 16 + 8 + f] = cosf(ang);
        }
    }
    for (int idx = tid; idx < ROWS * CTXC; idx += THREADS) {
        int c = idx >> 6, row = idx & 63;
        xS[row * XSTR + c] = ctxv[c * 32768 + rowBaseS[row]];
    }
    __syncthreads();

    // ---- MLP: 2 skip blocks of (156->96, 96->96, 96->96), all silu ----
    const int ng = tid & 15;
    const int rg = tid >> 4;
    const int r0 = rg * 4;
    const int n06 = ng * 6;

    const float* WP[6] = {w00, w01, w02, w10, w11, w12};
    const float* BP[6] = {b00, b01, b02, b10, b11, b12};

#pragma unroll 1
    for (int blk = 0; blk < 2; ++blk) {
        // Layer 0: [x ; coord] @ W0 + b0, silu -> hA
        loadW4(wS, WP[blk * 3 + 0], NIN0 * CTXC, tid);
        loadW4(bS, BP[blk * 3 + 0], CTXC, tid);
        __syncthreads();
        {
            float acc[4][6];
#pragma unroll
            for (int v = 0; v < 6; ++v) {
                float bb = bS[n06 + v];
                acc[0][v] = bb; acc[1][v] = bb; acc[2][v] = bb; acc[3][v] = bb;
            }
            mv_acc<6>(xS, XSTR, CTXC, wS, CTXC, n06, r0, acc);
            mv_acc<6>(coordS, CSTR, NCOORD, wS + CTXC * CTXC, CTXC, n06, r0, acc);
#pragma unroll
            for (int u = 0; u < 4; ++u)
#pragma unroll
                for (int v = 0; v < 6; ++v)
                    hA[(r0 + u) * XSTR + n06 + v] = silu(acc[u][v]);
        }
        __syncthreads();

        // Layer 1: hA -> hB
        loadW4(wS, WP[blk * 3 + 1], CTXC * CTXC, tid);
        loadW4(bS, BP[blk * 3 + 1], CTXC, tid);
        __syncthreads();
        {
            float acc[4][6];
#pragma unroll
            for (int v = 0; v < 6; ++v) {
                float bb = bS[n06 + v];
                acc[0][v] = bb; acc[1][v] = bb; acc[2][v] = bb; acc[3][v] = bb;
            }
            mv_acc<6>(hA, XSTR, CTXC, wS, CTXC, n06, r0, acc);
#pragma unroll
            for (int u = 0; u < 4; ++u)
#pragma unroll
                for (int v = 0; v < 6; ++v)
                    hB[(r0 + u) * XSTR + n06 + v] = silu(acc[u][v]);
        }
        __syncthreads();

        // Layer 2: hB -> hA
        loadW4(wS, WP[blk * 3 + 2], CTXC * CTXC, tid);
        loadW4(bS, BP[blk * 3 + 2], CTXC, tid);
        __syncthreads();
        {
            float acc[4][6];
#pragma unroll
            for (int v = 0; v < 6; ++v) {
                float bb = bS[n06 + v];
                acc[0][v] = bb; acc[1][v] = bb; acc[2][v] = bb; acc[3][v] = bb;
            }
            mv_acc<6>(hB, XSTR, CTXC, wS, CTXC, n06, r0, acc);
#pragma unroll
            for (int u = 0; u < 4; ++u)
#pragma unroll
                for (int v = 0; v < 6; ++v)
                    hA[(r0 + u) * XSTR + n06 + v] = silu(acc[u][v]);
        }
        __syncthreads();

        // Skip add: x += h
        for (int idx = tid; idx < ROWS * CTXC; idx += THREADS) {
            int row = idx / CTXC, c = idx - row * CTXC;
            xS[row * XSTR + c] += hA[row * XSTR + c];
        }
        __syncthreads();
    }

    // ---- Post layer: 96 -> 45 (padded to 48), no activation ----
    for (int idx = tid; idx < CTXC * 48; idx += THREADS) {
        int i = idx / 48, c = idx - i * 48;
        wS[idx] = (c < OUTC) ? pw[i * OUTC + c] : 0.0f;
    }
    if (tid < 48) bS[tid] = (tid < OUTC) ? pb[tid] : 0.0f;
    __syncthreads();
    {
        const int n03 = ng * 3;
        float acc[4][3];
#pragma unroll
        for (int v = 0; v < 3; ++v) {
            float bb = bS[n03 + v];
            acc[0][v] = bb; acc[1][v] = bb; acc[2][v] = bb; acc[3][v] = bb;
        }
        mv_acc<3>(xS, XSTR, CTXC, wS, 48, n03, r0, acc);
#pragma unroll
        for (int u = 0; u < 4; ++u)
#pragma unroll
            for (int v = 0; v < 3; ++v)
                hB[(r0 + u) * XSTR + n03 + v] = acc[u][v];
    }
    __syncthreads();

    // ---- Trilinear combine over 8 corners, write output ----
    for (int idx = tid; idx < OUTC * PTS; idx += THREADS) {
        int col = idx >> 3, pt = idx & 7;
        float a = 0.0f;
#pragma unroll
        for (int c8 = 0; c8 < 8; ++c8) {
            int row = pt * 8 + c8;
            a = fmaf(w8S[row], hB[row * XSTR + col], a);
        }
        out[col * QTOT + pbase + pt] = a;
    }
}

extern "C" void kernel_launch(void* const* d_in, const int* in_sizes, int n_in,
                              void* d_out, int out_size) {
    const float* ctxv = (const float*)d_in[0];   // context_v (1,96,32,32,32)
    const float* ext  = (const float*)d_in[1];   // context_spatial_extent (1,3,32,32,32)
    const float* qvs  = (const float*)d_in[2];   // query_vox_size (1,3)
    const float* qc   = (const float*)d_in[3];   // query_coord (1,3,48,48,48)
    const float* w00 = (const float*)d_in[4];
    const float* b00 = (const float*)d_in[5];
    const float* w01 = (const float*)d_in[6];
    const float* b01 = (const float*)d_in[7];
    const float* w02 = (const float*)d_in[8];
    const float* b02 = (const float*)d_in[9];
    const float* w10 = (const float*)d_in[10];
    const float* b10 = (const float*)d_in[11];
    const float* w11 = (const float*)d_in[12];
    const float* b11 = (const float*)d_in[13];
    const float* w12 = (const float*)d_in[14];
    const float* b12 = (const float*)d_in[15];
    const float* pw  = (const float*)d_in[16];
    const float* pb  = (const float*)d_in[17];
    float* out = (float*)d_out;

    cudaFuncSetAttribute(main_kernel, cudaFuncAttributeMaxDynamicSharedMemorySize, SMEM_BYTES);

    init_min_kernel<<<1, 32>>>();
    min_kernel<<<QTOT / 256, 256>>>(ext, qc);
    main_kernel<<<QTOT / PTS, THREADS, SMEM_BYTES>>>(
        ctxv, ext, qvs, qc,
        w00, b00, w01, b01, w02, b02,
        w10, b10, w11, b11, w12, b12,
        pw, pb, out);
}

// round 6
// speedup vs baseline: 1.0291x; 1.0291x over previous
#include <cuda_runtime.h>
#include <math.h>

// Problem constants (B=1, CX=CY=CZ=32, QX=QY=QZ=48)
#define QTOT   110592      // 48^3
#define CTXC   96
#define NCOORD 60
#define NIN0   156         // CTXC + NCOORD
#define OUTC   45
#define PTS    8           // points per CTA
#define ROWS   64          // PTS * 8 corners
#define XSTR   97          // padded stride for 96-wide activation buffers
#define CSTR   61          // padded stride for coord features
#define THREADS 256

// Shared memory layout (in floats); all offsets multiple of 4 for 16B copies
#define OFF_X    0
#define OFF_HA   (ROWS*XSTR)            // 6208
#define OFF_HB   (2*ROWS*XSTR)          // 12416
#define OFF_C    (3*ROWS*XSTR)          // 18624
#define OFF_W0   (OFF_C + ROWS*CSTR)    // 22528
#define WBUF     (NIN0*CTXC)            // 14976 floats per weight buffer
#define OFF_W1   (OFF_W0 + WBUF)        // 37504
#define OFF_PB   (OFF_W0 + 2*WBUF)      // 52480  post bias (48)
#define OFF_W8   (OFF_PB + 48)          // 52528  trilinear weights (64)
#define OFF_PT   (OFF_W8 + ROWS)        // 52592  t factors (24)
#define OFF_PQ   (OFF_PT + 24)          // ptQ (24)
#define OFF_PR   (OFF_PQ + 24)          // raw rel000 (24)
#define OFF_MISC (OFF_PR + 24)          // qv[3], vox[3], min[3] (+pad)
#define OFF_INT  (OFF_MISC + 12)        // ints: near[24], rowBase[64]
#define SMEM_FLOATS (OFF_INT + 24 + 64)
#define SMEM_BYTES  (SMEM_FLOATS * 4)

typedef unsigned long long u64t;

__device__ unsigned int g_min_enc[3];

__device__ __forceinline__ unsigned fenc(float f) {
    unsigned u = __float_as_uint(f);
    return (u & 0x80000000u) ? ~u : (u | 0x80000000u);
}
__device__ __forceinline__ float fdec(unsigned e) {
    return __uint_as_float((e & 0x80000000u) ? (e ^ 0x80000000u) : ~e);
}
__device__ __forceinline__ float silu(float x) {
    return x * (1.0f / (1.0f + __expf(-x)));
}

// ---- packed f32x2 helpers (FFMA2 path; ptxas never emits it from C++) ----
__device__ __forceinline__ u64t pack2s(float a) {
    u64t r; unsigned u = __float_as_uint(a);
    asm("mov.b64 %0, {%1, %2};" : "=l"(r) : "r"(u), "r"(u));
    return r;
}
__device__ __forceinline__ u64t pack2f(float lo, float hi) {
    u64t r; unsigned ulo = __float_as_uint(lo), uhi = __float_as_uint(hi);
    asm("mov.b64 %0, {%1, %2};" : "=l"(r) : "r"(ulo), "r"(uhi));
    return r;
}
__device__ __forceinline__ void fma2(u64t& d, u64t a, u64t b) {
    asm("fma.rn.f32x2 %0, %1, %2, %0;" : "+l"(d) : "l"(a), "l"(b));
}
__device__ __forceinline__ float2 unpack2(u64t v) {
    unsigned lo, hi;
    asm("mov.b64 {%0, %1}, %2;" : "=r"(lo), "=r"(hi) : "l"(v));
    return make_float2(__uint_as_float(lo), __uint_as_float(hi));
}

__global__ void init_min_kernel() {
    if (threadIdx.x < 3) g_min_enc[threadIdx.x] = 0xFFFFFFFFu;
}

// Global min over raw rel000 (pre-clamp) per dim. Clamp is applied later (monotone).
__global__ void min_kernel(const float* __restrict__ ext, const float* __restrict__ qc) {
    int p = blockIdx.x * blockDim.x + threadIdx.x;
    float raw[3] = {1e30f, 1e30f, 1e30f};
    if (p < QTOT) {
        int ni[3];
        float q[3];
#pragma unroll
        for (int d = 0; d < 3; d++) {
            float o = ext[d * 32768];
            float v = fabsf(ext[d * 32768 + 1057] - o);
            q[d] = qc[d * QTOT + p];
            int n = __float2int_rn((q[d] - o) / v);
            ni[d] = min(max(n, 0), 30);
        }
#pragma unroll
        for (int d = 0; d < 3; d++) {
            float cc = ext[d * 32768 + ni[0] * 1024 + ni[1] * 32 + ni[2]];
            raw[d] = cc - q[d];
        }
    }
#pragma unroll
    for (int off = 16; off; off >>= 1) {
#pragma unroll
        for (int d = 0; d < 3; d++)
            raw[d] = fminf(raw[d], __shfl_down_sync(0xffffffffu, raw[d], off));
    }
    if ((threadIdx.x & 31) == 0) {
#pragma unroll
        for (int d = 0; d < 3; d++)
            atomicMin(&g_min_enc[d], fenc(raw[d]));
    }
}

// Packed matvec accumulate: 4 rows x NP neuron-pairs per thread (FFMA2).
template <int NP>
__device__ __forceinline__ void mv_acc2(const float* __restrict__ in, int istr, int n_in,
                                        const float* __restrict__ w, int wstr, int n0,
                                        int r0, u64t (&acc)[4][NP]) {
#pragma unroll 4
    for (int i = 0; i < n_in; ++i) {
        u64t a0 = pack2s(in[(r0 + 0) * istr + i]);
        u64t a1 = pack2s(in[(r0 + 1) * istr + i]);
        u64t a2 = pack2s(in[(r0 + 2) * istr + i]);
        u64t a3 = pack2s(in[(r0 + 3) * istr + i]);
        const u64t* wr = (const u64t*)(w + i * wstr + n0);
#pragma unroll
        for (int v = 0; v < NP; ++v) {
            u64t wv = wr[v];
            fma2(acc[0][v], a0, wv);
            fma2(acc[1][v], a1, wv);
            fma2(acc[2][v], a2, wv);
            fma2(acc[3][v], a3, wv);
        }
    }
}

// Scalar matvec for the post layer (odd widths): 4 rows x NT neurons.
template <int NT>
__device__ __forceinline__ void mv_acc(const float* __restrict__ in, int istr, int n_in,
                                       const float* __restrict__ w, int wstr, int n0,
                                       int r0, float (&acc)[4][NT]) {
#pragma unroll 4
    for (int i = 0; i < n_in; ++i) {
        float a0 = in[(r0 + 0) * istr + i];
        float a1 = in[(r0 + 1) * istr + i];
        float a2 = in[(r0 + 2) * istr + i];
        float a3 = in[(r0 + 3) * istr + i];
        const float* wr = w + i * wstr + n0;
#pragma unroll
        for (int v = 0; v < NT; ++v) {
            float wv = wr[v];
            acc[0][v] = fmaf(a0, wv, acc[0][v]);
            acc[1][v] = fmaf(a1, wv, acc[1][v]);
            acc[2][v] = fmaf(a2, wv, acc[2][v]);
            acc[3][v] = fmaf(a3, wv, acc[3][v]);
        }
    }
}

// Async stage: gmem -> smem, 16B chunks (LDGSTS). Caller commits/waits.
__device__ __forceinline__ void stage_async(float* dst, const float* __restrict__ src,
                                            int nfloats, int tid) {
    unsigned sbase = (unsigned)__cvta_generic_to_shared(dst);
    int nchunk = nfloats >> 2;
    for (int i = tid; i < nchunk; i += THREADS)
        asm volatile("cp.async.cg.shared.global [%0], [%1], 16;"
                     :: "r"(sbase + i * 16), "l"(src + i * 4) : "memory");
}
__device__ __forceinline__ void cp_commit() {
    asm volatile("cp.async.commit_group;" ::: "memory");
}
__device__ __forceinline__ void cp_wait0() {
    asm volatile("cp.async.wait_group 0;" ::: "memory");
}

__global__ __launch_bounds__(THREADS, 1) void main_kernel(
    const float* __restrict__ ctxv, const float* __restrict__ ext,
    const float* __restrict__ qvs, const float* __restrict__ qc,
    const float* __restrict__ w00, const float* __restrict__ b00,
    const float* __restrict__ w01, const float* __restrict__ b01,
    const float* __restrict__ w02, const float* __restrict__ b02,
    const float* __restrict__ w10, const float* __restrict__ b10,
    const float* __restrict__ w11, const float* __restrict__ b11,
    const float* __restrict__ w12, const float* __restrict__ b12,
    const float* __restrict__ pw, const float* __restrict__ pb,
    float* __restrict__ out) {
    extern __shared__ float sm[];
    float* xS = sm + OFF_X;
    float* hA = sm + OFF_HA;
    float* hB = sm + OFF_HB;
    float* coordS = sm + OFF_C;
    float* wBuf[2] = {sm + OFF_W0, sm + OFF_W1};
    float* pbS = sm + OFF_PB;
    float* w8S = sm + OFF_W8;
    float* ptT = sm + OFF_PT;
    float* ptQ = sm + OFF_PQ;
    float* ptR = sm + OFF_PR;
    float* qvS = sm + OFF_MISC;
    float* voxS = qvS + 3;
    float* minS = voxS + 3;
    int* nearS = (int*)(sm + OFF_INT);
    int* rowBaseS = nearS + 24;

    const int tid = threadIdx.x;
    const int pbase = blockIdx.x * PTS;

    const float* WP[6] = {w00, w01, w02, w10, w11, w12};
    const float* BP[6] = {b00, b01, b02, b10, b11, b12};

    // Kick off async stage of layer-0 weights; overlaps with feature setup.
    stage_async(wBuf[0], w00, NIN0 * CTXC, tid);
    cp_commit();

    // ---- Region 1: per-dim constants + per-point nearest ----
    if (tid < 3) {
        float o = ext[tid * 32768];
        qvS[tid] = qvs[tid];
        voxS[tid] = fabsf(ext[tid * 32768 + 1057] - o);
        minS[tid] = fdec(g_min_enc[tid]);
    }
    if (tid < 24) {
        int pt = tid / 3, d = tid - pt * 3;
        float o = ext[d * 32768];
        float v = fabsf(ext[d * 32768 + 1057] - o);
        float q = qc[d * QTOT + pbase + pt];
        int n = __float2int_rn((q - o) / v);
        nearS[tid] = min(max(n, 0), 30);
        ptQ[tid] = q;
    }
    __syncthreads();

    // ---- Region 2: raw rel000, trilinear t, per-row gather base ----
    if (tid < 24) {
        int pt = tid / 3, d = tid - pt * 3;
        float cc = ext[d * 32768 + nearS[pt * 3] * 1024 + nearS[pt * 3 + 1] * 32 + nearS[pt * 3 + 2]];
        float raw = cc - ptQ[tid];
        ptR[tid] = raw;
        float v = voxS[d];
        float clampc = fmaf(v, -0.5f, 1e-7f);
        float rel0 = fmaxf(raw, clampc);
        float g = fminf(fmaxf((rel0 - 0.5f) * 2.0f, -1.0f + 1e-7f), 1.0f - 1e-7f);
        ptT[tid] = (g + 1.0f) * 0.5f;
    }
    if (tid < ROWS) {
        int pt = tid >> 3, cn = tid & 7;
        int ix = nearS[pt * 3 + 0] + ((cn >> 2) & 1);
        int iy = nearS[pt * 3 + 1] + ((cn >> 1) & 1);
        int iz = nearS[pt * 3 + 2] + (cn & 1);
        rowBaseS[tid] = ix * 1024 + iy * 32 + iz;
    }
    __syncthreads();

    // ---- Region 3: trilinear weights, coord features, context gather ----
    if (tid < ROWS) {
        int pt = tid >> 3, cn = tid & 7;
        // Reference mapping: corner i (dim0) uses t[dim2], j uses t[dim1], k uses t[dim0]
        float wi = ((cn >> 2) & 1) ? ptT[pt * 3 + 2] : 1.0f - ptT[pt * 3 + 2];
        float wj = ((cn >> 1) & 1) ? ptT[pt * 3 + 1] : 1.0f - ptT[pt * 3 + 1];
        float wk = (cn & 1) ? ptT[pt * 3 + 0] : 1.0f - ptT[pt * 3 + 0];
        w8S[tid] = wi * wj * wk;
    }
    if (tid < ROWS * 3) {
        int row = tid / 3, d = tid - row * 3;
        int pt = row >> 3, cn = row & 7;
        int off = (d == 0) ? ((cn >> 2) & 1) : (d == 1) ? ((cn >> 1) & 1) : (cn & 1);
        float v = voxS[d];
        float clampc = fmaf(v, -0.5f, 1e-7f);
        float raw = ptR[pt * 3 + d] + (float)off * v;
        float rel = fmaxf(raw, clampc);
        float rmin = fmaxf(minS[d] + (float)off * v, clampc);
        float rn = (rel - rmin) / (1.5f * v);
        float cc = ext[d * 32768 + rowBaseS[row]];
        float* cf = coordS + row * CSTR;
        cf[0 + d] = qvS[d];
        cf[3 + d] = cc;
        cf[6 + d] = ptQ[pt * 3 + d];
        cf[9 + d] = rn;
        const float TWO_PI = 6.2831853071795864769f;
#pragma unroll
        for (int f = 0; f < 8; ++f) {
            float fr = exp2f((float)f * 0.29024101186092026f);  // 5^(f/8)
            float ang = TWO_PI * rn * fr;
            cf[12 + d * 16 + f] = sinf(ang);
            cf[12 + d * 16 + 8 + f] = cosf(ang);
        }
    }
    for (int idx = tid; idx < ROWS * CTXC; idx += THREADS) {
        int c = idx >> 6, row = idx & 63;
        xS[row * XSTR + c] = ctxv[c * 32768 + rowBaseS[row]];
    }
    __syncthreads();

    // ---- MLP: 2 skip blocks of (156->96, 96->96, 96->96), all silu ----
    const int ng = tid & 15;
    const int rg = tid >> 4;
    const int r0 = rg * 4;
    const int n06 = ng * 6;

    int cur = 0;
#pragma unroll 1
    for (int blk = 0; blk < 2; ++blk) {
#pragma unroll 1
        for (int l = 0; l < 3; ++l) {
            int lidx = blk * 3 + l;
            // Weights for this layer finished staging; make them visible.
            cp_wait0();
            __syncthreads();
            // Prefetch next layer's weights into the other buffer (overlaps compute).
            if (lidx < 5) {
                int nn = (lidx == 5 - 1 && false) ? 0 : ((lidx + 1) % 3 == 0 ? NIN0 * CTXC : CTXC * CTXC);
                stage_async(wBuf[cur ^ 1], WP[lidx + 1], nn, tid);
            }
            cp_commit();

            const float* wcur = wBuf[cur];
            const float* inA = (l == 0) ? xS : ((l == 1) ? hA : hB);
            float* outB = (l == 1) ? hB : hA;

            u64t acc[4][3];
            {
                const float2* bb = (const float2*)BP[lidx];
#pragma unroll
                for (int v = 0; v < 3; ++v) {
                    float2 b2 = __ldg(&bb[ng * 3 + v]);
                    u64t pbk = pack2f(b2.x, b2.y);
                    acc[0][v] = pbk; acc[1][v] = pbk; acc[2][v] = pbk; acc[3][v] = pbk;
                }
            }
            mv_acc2<3>(inA, XSTR, CTXC, wcur, CTXC, n06, r0, acc);
            if (l == 0)
                mv_acc2<3>(coordS, CSTR, NCOORD, wcur + CTXC * CTXC, CTXC, n06, r0, acc);
#pragma unroll
            for (int u = 0; u < 4; ++u)
#pragma unroll
                for (int v = 0; v < 3; ++v) {
                    float2 rr = unpack2(acc[u][v]);
                    outB[(r0 + u) * XSTR + n06 + 2 * v] = silu(rr.x);
                    outB[(r0 + u) * XSTR + n06 + 2 * v + 1] = silu(rr.y);
                }
            __syncthreads();
            cur ^= 1;
        }

        // Skip add: x += h (h is in hA after layer 2)
        for (int idx = tid; idx < ROWS * CTXC; idx += THREADS) {
            int row = idx / CTXC, c = idx - row * CTXC;
            xS[row * XSTR + c] += hA[row * XSTR + c];
        }
        __syncthreads();
    }

    // ---- Post layer: 96 -> 45 (padded to 48), no activation ----
    // cur == 0 here; wBuf[0]'s last reader (layer idx4) synced long ago.
    {
        float* wS = wBuf[0];
        for (int idx = tid; idx < CTXC * 48; idx += THREADS) {
            int i = idx / 48, c = idx - i * 48;
            wS[idx] = (c < OUTC) ? pw[i * OUTC + c] : 0.0f;
        }
        if (tid < 48) pbS[tid] = (tid < OUTC) ? pb[tid] : 0.0f;
        __syncthreads();
        const int n03 = ng * 3;
        float acc[4][3];
#pragma unroll
        for (int v = 0; v < 3; ++v) {
            float bbv = pbS[n03 + v];
            acc[0][v] = bbv; acc[1][v] = bbv; acc[2][v] = bbv; acc[3][v] = bbv;
        }
        mv_acc<3>(xS, XSTR, CTXC, wS, 48, n03, r0, acc);
#pragma unroll
        for (int u = 0; u < 4; ++u)
#pragma unroll
            for (int v = 0; v < 3; ++v)
                hB[(r0 + u) * XSTR + n03 + v] = acc[u][v];
    }
    __syncthreads();

    // ---- Trilinear combine over 8 corners, write output ----
    for (int idx = tid; idx < OUTC * PTS; idx += THREADS) {
        int col = idx >> 3, pt = idx & 7;
        float a = 0.0f;
#pragma unroll
        for (int c8 = 0; c8 < 8; ++c8) {
            int row = pt * 8 + c8;
            a = fmaf(w8S[row], hB[row * XSTR + col], a);
        }
        out[col * QTOT + pbase + pt] = a;
    }
}

extern "C" void kernel_launch(void* const* d_in, const int* in_sizes, int n_in,
                              void* d_out, int out_size) {
    const float* ctxv = (const float*)d_in[0];   // context_v (1,96,32,32,32)
    const float* ext  = (const float*)d_in[1];   // context_spatial_extent (1,3,32,32,32)
    const float* qvs  = (const float*)d_in[2];   // query_vox_size (1,3)
    const float* qc   = (const float*)d_in[3];   // query_coord (1,3,48,48,48)
    const float* w00 = (const float*)d_in[4];
    const float* b00 = (const float*)d_in[5];
    const float* w01 = (const float*)d_in[6];
    const float* b01 = (const float*)d_in[7];
    const float* w02 = (const float*)d_in[8];
    const float* b02 = (const float*)d_in[9];
    const float* w10 = (const float*)d_in[10];
    const float* b10 = (const float*)d_in[11];
    const float* w11 = (const float*)d_in[12];
    const float* b11 = (const float*)d_in[13];
    const float* w12 = (const float*)d_in[14];
    const float* b12 = (const float*)d_in[15];
    const float* pw  = (const float*)d_in[16];
    const float* pb  = (const float*)d_in[17];
    float* out = (float*)d_out;

    cudaFuncSetAttribute(main_kernel, cudaFuncAttributeMaxDynamicSharedMemorySize, SMEM_BYTES);

    init_min_kernel<<<1, 32>>>();
    min_kernel<<<QTOT / 256, 256>>>(ext, qc);
    main_kernel<<<QTOT / PTS, THREADS, SMEM_BYTES>>>(
        ctxv, ext, qvs, qc,
        w00, b00, w01, b01, w02, b02,
        w10, b10, w11, b11, w12, b12,
        pw, pb, out);
}

// round 8
// speedup vs baseline: 1.2664x; 1.2307x over previous
#include <cuda_runtime.h>
#include <math.h>

// Problem constants (B=1, CX=CY=CZ=32, QX=QY=QZ=48)
#define QTOT   110592      // 48^3
#define CTXC   96
#define OUTC   45
#define PTS    4           // points per CTA
#define ROWS   32          // PTS * 8 corners
#define XSTR   100         // act row stride (floats), mult of 4
#define CSTR   60          // coord row stride (floats), mult of 4
#define ISTRM  100         // transposed weight i-stride, mid layers (96 padded)
#define ISTR0  164         // transposed weight i-stride, 156-input layers (padded)
#define THREADS 256

// Shared memory layout (floats)
#define OFF_X    0                       // 32*100 = 3200
#define OFF_HA   3200
#define OFF_HB   6400
#define OFF_C    9600                    // 32*60 = 1920
#define OFF_W    11520                   // 96*164 = 15744
#define OFF_W8   27264                   // 32
#define OFF_PT   27296                   // 12
#define OFF_PQ   27308                   // 12
#define OFF_PR   27320                   // 12
#define OFF_MISC 27332                   // qv3 vox3 min3 (+pad)
#define OFF_INT  27344                   // ints: near[12], rowBase[32]
#define SMEM_FLOATS (OFF_INT + 12 + 32)
#define SMEM_BYTES  (SMEM_FLOATS * 4)

typedef unsigned long long u64t;

__device__ unsigned int g_min_enc[3];

__device__ __forceinline__ unsigned fenc(float f) {
    unsigned u = __float_as_uint(f);
    return (u & 0x80000000u) ? ~u : (u | 0x80000000u);
}
__device__ __forceinline__ float fdec(unsigned e) {
    return __uint_as_float((e & 0x80000000u) ? (e ^ 0x80000000u) : ~e);
}
__device__ __forceinline__ float silu(float x) {
    return x * (1.0f / (1.0f + __expf(-x)));
}

// packed f32x2 FMA (FFMA2): both operands are natural 64-bit pairs.
__device__ __forceinline__ void fma2(u64t& d, u64t a, u64t b) {
    asm("fma.rn.f32x2 %0, %1, %2, %0;" : "+l"(d) : "l"(a), "l"(b));
}
__device__ __forceinline__ float2 unpack2(u64t v) {
    unsigned lo, hi;
    asm("mov.b64 {%0, %1}, %2;" : "=r"(lo), "=r"(hi) : "l"(v));
    return make_float2(__uint_as_float(lo), __uint_as_float(hi));
}
// 16B shared load directly into two 64-bit regs (zero pack MOVs).
__device__ __forceinline__ void lds2(u64t& a, u64t& b, unsigned addr) {
    asm("ld.shared.v2.u64 {%0, %1}, [%2];" : "=l"(a), "=l"(b) : "r"(addr));
}

__global__ void init_min_kernel() {
    if (threadIdx.x < 3) g_min_enc[threadIdx.x] = 0xFFFFFFFFu;
}

// Global min over raw rel000 (pre-clamp) per dim. Clamp applied later (monotone).
__global__ void min_kernel(const float* __restrict__ ext, const float* __restrict__ qc) {
    int p = blockIdx.x * blockDim.x + threadIdx.x;
    float raw[3] = {1e30f, 1e30f, 1e30f};
    if (p < QTOT) {
        int ni[3];
        float q[3];
#pragma unroll
        for (int d = 0; d < 3; d++) {
            float o = ext[d * 32768];
            float v = fabsf(ext[d * 32768 + 1057] - o);
            q[d] = qc[d * QTOT + p];
            int n = __float2int_rn((q[d] - o) / v);
            ni[d] = min(max(n, 0), 30);
        }
#pragma unroll
        for (int d = 0; d < 3; d++) {
            float cc = ext[d * 32768 + ni[0] * 1024 + ni[1] * 32 + ni[2]];
            raw[d] = cc - q[d];
        }
    }
#pragma unroll
    for (int off = 16; off; off >>= 1) {
#pragma unroll
        for (int d = 0; d < 3; d++)
            raw[d] = fminf(raw[d], __shfl_down_sync(0xffffffffu, raw[d], off));
    }
    if ((threadIdx.x & 31) == 0) {
#pragma unroll
        for (int d = 0; d < 3; d++)
            atomicMin(&g_min_enc[d], fenc(raw[d]));
    }
}

// Matvec partial: 2 rows x 6 neurons per thread, FFMA2 paired along i.
__device__ __forceinline__ void mm_part6(u64t (&acc)[2][6], unsigned aA, unsigned aB,
                                         unsigned wbase, unsigned wstr, int nin) {
#pragma unroll 2
    for (int i = 0; i < nin; i += 4) {
        u64t x0, x1, y0, y1;
        lds2(x0, x1, aA + i * 4);
        lds2(y0, y1, aB + i * 4);
#pragma unroll
        for (int v = 0; v < 6; ++v) {
            u64t w0, w1;
            lds2(w0, w1, wbase + v * wstr + i * 4);
            fma2(acc[0][v], x0, w0); fma2(acc[0][v], x1, w1);
            fma2(acc[1][v], y0, w0); fma2(acc[1][v], y1, w1);
        }
    }
}

// Staging (register-carried): global [96][96] row-major -> smem wT[n][i] transposed.
__device__ __forceinline__ void stage_load_96(float4 (&st)[9], const float* __restrict__ src, int tid) {
#pragma unroll
    for (int j = 0; j < 9; ++j) {
        int c = tid + j * 256;
        int i4 = c / 96, n = c - i4 * 96;
        const float* s = src + i4 * 4 * 96 + n;
        st[j].x = s[0]; st[j].y = s[96]; st[j].z = s[192]; st[j].w = s[288];
    }
}
__device__ __forceinline__ void stage_store_96(const float4 (&st)[9], float* wT, int tid) {
#pragma unroll
    for (int j = 0; j < 9; ++j) {
        int c = tid + j * 256;
        int i4 = c / 96, n = c - i4 * 96;
        *(float4*)(wT + n * ISTRM + i4 * 4) = st[j];
    }
}
// 156-input layer: [156][96] row-major -> wT[n][i], stride ISTR0.
__device__ __forceinline__ void stage_load_156(float4 (&st)[15], const float* __restrict__ src, int tid) {
#pragma unroll
    for (int j = 0; j < 15; ++j) {
        int c = tid + j * 256;
        float4 t = make_float4(0.f, 0.f, 0.f, 0.f);
        if (c < 3744) {
            int i4 = c / 96, n = c - i4 * 96;
            const float* s = src + i4 * 4 * 96 + n;
            t.x = s[0]; t.y = s[96]; t.z = s[192]; t.w = s[288];
        }
        st[j] = t;
    }
}
__device__ __forceinline__ void stage_store_156(const float4 (&st)[15], float* wT, int tid) {
#pragma unroll
    for (int j = 0; j < 15; ++j) {
        int c = tid + j * 256;
        if (c < 3744) {
            int i4 = c / 96, n = c - i4 * 96;
            *(float4*)(wT + n * ISTR0 + i4 * 4) = st[j];
        }
    }
}
// post: pw [96][45] -> wT[48][ISTRM] zero-padded
__device__ __forceinline__ void stage_load_post(float4 (&st)[5], const float* __restrict__ pw, int tid) {
#pragma unroll
    for (int j = 0; j < 5; ++j) {
        int c = tid + j * 256;
        float4 t = make_float4(0.f, 0.f, 0.f, 0.f);
        if (c < 1152) {
            int i4 = c / 48, n = c - i4 * 48;
            if (n < OUTC) {
                t.x = pw[(i4 * 4 + 0) * OUTC + n];
                t.y = pw[(i4 * 4 + 1) * OUTC + n];
                t.z = pw[(i4 * 4 + 2) * OUTC + n];
                t.w = pw[(i4 * 4 + 3) * OUTC + n];
            }
        }
        st[j] = t;
    }
}
__device__ __forceinline__ void stage_store_post(const float4 (&st)[5], float* wT, int tid) {
#pragma unroll
    for (int j = 0; j < 5; ++j) {
        int c = tid + j * 256;
        if (c < 1152) {
            int i4 = c / 48, n = c - i4 * 48;
            *(float4*)(wT + n * ISTRM + i4 * 4) = st[j];
        }
    }
}

__global__ __launch_bounds__(THREADS, 2) void main_kernel(
    const float* __restrict__ ctxv, const float* __restrict__ ext,
    const float* __restrict__ qvs, const float* __restrict__ qc,
    const float* __restrict__ w00, const float* __restrict__ b00,
    const float* __restrict__ w01, const float* __restrict__ b01,
    const float* __restrict__ w02, const float* __restrict__ b02,
    const float* __restrict__ w10, const float* __restrict__ b10,
    const float* __restrict__ w11, const float* __restrict__ b11,
    const float* __restrict__ w12, const float* __restrict__ b12,
    const float* __restrict__ pw, const float* __restrict__ pb,
    float* __restrict__ out) {
    extern __shared__ float sm[];
    float* xS = sm + OFF_X;
    float* hA = sm + OFF_HA;
    float* hB = sm + OFF_HB;
    float* coordS = sm + OFF_C;
    float* wS = sm + OFF_W;
    float* w8S = sm + OFF_W8;
    float* ptT = sm + OFF_PT;
    float* ptQ = sm + OFF_PQ;
    float* ptR = sm + OFF_PR;
    float* qvS = sm + OFF_MISC;
    float* voxS = qvS + 3;
    float* minS = voxS + 3;
    int* nearS = (int*)(sm + OFF_INT);
    int* rowBaseS = nearS + 12;

    const int tid = threadIdx.x;
    const int pbase = blockIdx.x * PTS;
    const unsigned smb = (unsigned)__cvta_generic_to_shared(sm);
    const unsigned xA = smb + OFF_X * 4;
    const unsigned hAA = smb + OFF_HA * 4;
    const unsigned hBA = smb + OFF_HB * 4;
    const unsigned cAbase = smb + OFF_C * 4;
    const unsigned wA = smb + OFF_W * 4;

    const int lane = tid & 31;
    const int warp = tid >> 5;
    const int nq = lane & 1;
    const int rq = lane >> 1;       // 0..15
    const int r0 = rq, r1 = rq + 16;
    const int n0 = warp * 12 + nq * 6;   // 6 neurons n0..n0+5

    // ---- Stage layer-0 weights (transposed) into regs early; LDG latency
    // overlaps the feature-setup work below ----
    float4 st0[15];
    stage_load_156(st0, w00, tid);

    // ---- Region 1 ----
    if (tid < 3) {
        float o = ext[tid * 32768];
        qvS[tid] = qvs[tid];
        voxS[tid] = fabsf(ext[tid * 32768 + 1057] - o);
        minS[tid] = fdec(g_min_enc[tid]);
    }
    if (tid < 12) {
        int pt = tid / 3, d = tid - pt * 3;
        float o = ext[d * 32768];
        float v = fabsf(ext[d * 32768 + 1057] - o);
        float q = qc[d * QTOT + pbase + pt];
        int n = __float2int_rn((q - o) / v);
        nearS[tid] = min(max(n, 0), 30);
        ptQ[tid] = q;
    }
    __syncthreads();

    // ---- Region 2: raw rel000, trilinear t, per-row gather base ----
    if (tid < 12) {
        int pt = tid / 3, d = tid - pt * 3;
        float cc = ext[d * 32768 + nearS[pt * 3] * 1024 + nearS[pt * 3 + 1] * 32 + nearS[pt * 3 + 2]];
        float raw = cc - ptQ[tid];
        ptR[tid] = raw;
        float v = voxS[d];
        float clampc = fmaf(v, -0.5f, 1e-7f);
        float rel0 = fmaxf(raw, clampc);
        float g = fminf(fmaxf((rel0 - 0.5f) * 2.0f, -1.0f + 1e-7f), 1.0f - 1e-7f);
        ptT[tid] = (g + 1.0f) * 0.5f;
    }
    if (tid < ROWS) {
        int pt = tid >> 3, cn = tid & 7;
        int ix = nearS[pt * 3 + 0] + ((cn >> 2) & 1);
        int iy = nearS[pt * 3 + 1] + ((cn >> 1) & 1);
        int iz = nearS[pt * 3 + 2] + (cn & 1);
        rowBaseS[tid] = ix * 1024 + iy * 32 + iz;
    }
    __syncthreads();

    // ---- Region 3: trilinear weights, coord features, context gather ----
    if (tid < ROWS) {
        int pt = tid >> 3, cn = tid & 7;
        float wi = ((cn >> 2) & 1) ? ptT[pt * 3 + 2] : 1.0f - ptT[pt * 3 + 2];
        float wj = ((cn >> 1) & 1) ? ptT[pt * 3 + 1] : 1.0f - ptT[pt * 3 + 1];
        float wk = (cn & 1) ? ptT[pt * 3 + 0] : 1.0f - ptT[pt * 3 + 0];
        w8S[tid] = wi * wj * wk;
    }
    if (tid < ROWS * 3) {
        int row = tid / 3, d = tid - row * 3;
        int pt = row >> 3, cn = row & 7;
        int off = (d == 0) ? ((cn >> 2) & 1) : (d == 1) ? ((cn >> 1) & 1) : (cn & 1);
        float v = voxS[d];
        float clampc = fmaf(v, -0.5f, 1e-7f);
        float raw = ptR[pt * 3 + d] + (float)off * v;
        float rel = fmaxf(raw, clampc);
        float rmin = fmaxf(minS[d] + (float)off * v, clampc);
        float rn = (rel - rmin) / (1.5f * v);
        float cc = ext[d * 32768 + rowBaseS[row]];
        float* cf = coordS + row * CSTR;
        cf[0 + d] = qvS[d];
        cf[3 + d] = cc;
        cf[6 + d] = ptQ[pt * 3 + d];
        cf[9 + d] = rn;
        const float TWO_PI = 6.2831853071795864769f;
#pragma unroll
        for (int f = 0; f < 8; ++f) {
            float fr = exp2f((float)f * 0.29024101186092026f);  // 5^(f/8)
            float ang = TWO_PI * rn * fr;
            cf[12 + d * 16 + f] = sinf(ang);
            cf[12 + d * 16 + 8 + f] = cosf(ang);
        }
    }
    // context gather: warp sweeps rows for fixed channel (corner pairs share sectors)
    for (int idx = tid; idx < ROWS * CTXC; idx += THREADS) {
        int row = idx & 31, c = idx >> 5;
        xS[row * XSTR + c] = ctxv[c * 32768 + rowBaseS[row]];
    }
    // store layer-0 transposed weights
    stage_store_156(st0, wS, tid);
    __syncthreads();

    // ---- MLP: 2 skip blocks of (156->96, 96->96, 96->96), all silu ----
    const float* WPn[5] = {w01, w02, w10, w11, w12};  // source of layer lidx+1
    const float* BP[6] = {b00, b01, b02, b10, b11, b12};

#pragma unroll 1
    for (int blk = 0; blk < 2; ++blk) {
#pragma unroll 1
        for (int l = 0; l < 3; ++l) {
            int lidx = blk * 3 + l;
            // prefetch next weights into regs (hidden behind matvec).
            // lidx==2's successor (w10) is 156-wide: handled synchronously below.
            float4 stm[9];
            float4 stp[5];
            bool midnext = (lidx == 0 || lidx == 1 || lidx == 3 || lidx == 4);
            bool postnext = (lidx == 5);
            if (midnext) stage_load_96(stm, WPn[lidx], tid);
            else if (postnext) stage_load_post(stp, pw, tid);

            unsigned inA = (l == 0) ? xA : ((l == 1) ? hAA : hBA);
            float* outP = (l == 1) ? hB : hA;
            unsigned wstr = (l == 0) ? (ISTR0 * 4) : (ISTRM * 4);
            unsigned wbase = wA + n0 * wstr;

            u64t acc[2][6];
#pragma unroll
            for (int v = 0; v < 6; ++v) { acc[0][v] = 0ull; acc[1][v] = 0ull; }

            mm_part6(acc, inA + r0 * (XSTR * 4), inA + r1 * (XSTR * 4), wbase, wstr, CTXC);
            if (l == 0)
                mm_part6(acc, cAbase + r0 * (CSTR * 4), cAbase + r1 * (CSTR * 4),
                         wbase + 96 * 4, wstr, CSTR);

            const float* bp = BP[lidx];
#pragma unroll
            for (int v = 0; v < 6; ++v) {
                float b = __ldg(bp + n0 + v);
                float2 e0 = unpack2(acc[0][v]);
                float2 e1 = unpack2(acc[1][v]);
                outP[r0 * XSTR + n0 + v] = silu(e0.x + e0.y + b);
                outP[r1 * XSTR + n0 + v] = silu(e1.x + e1.y + b);
            }
            __syncthreads();   // wS free + outP ready
            if (midnext) {
                stage_store_96(stm, wS, tid);
            } else if (postnext) {
                stage_store_post(stp, wS, tid);
            } else {
                // lidx == 2: synchronous full stage of the 156-wide w10
                float4 stb[15];
                stage_load_156(stb, w10, tid);
                stage_store_156(stb, wS, tid);
            }
            __syncthreads();   // new weights visible
        }

        // Skip add: x += h (h in hA after layer 2)
        for (int idx = tid; idx < ROWS * CTXC; idx += THREADS) {
            int row = idx / CTXC, c = idx - row * CTXC;
            xS[row * XSTR + c] += hA[row * XSTR + c];
        }
        __syncthreads();
    }

    // ---- Post layer: 96 -> 45 (48-padded), no activation ----
    {
        const int n0p = warp * 6 + nq * 3;   // 3 neurons
        u64t acc[2][3];
#pragma unroll
        for (int v = 0; v < 3; ++v) { acc[0][v] = 0ull; acc[1][v] = 0ull; }
        unsigned wbase = wA + n0p * (ISTRM * 4);
#pragma unroll 2
        for (int i = 0; i < CTXC; i += 4) {
            u64t x0, x1, y0, y1;
            lds2(x0, x1, xA + r0 * (XSTR * 4) + i * 4);
            lds2(y0, y1, xA + r1 * (XSTR * 4) + i * 4);
#pragma unroll
            for (int v = 0; v < 3; ++v) {
                u64t w0, w1;
                lds2(w0, w1, wbase + v * (ISTRM * 4) + i * 4);
                fma2(acc[0][v], x0, w0); fma2(acc[0][v], x1, w1);
                fma2(acc[1][v], y0, w0); fma2(acc[1][v], y1, w1);
            }
        }
#pragma unroll
        for (int v = 0; v < 3; ++v) {
            int n = n0p + v;
            float b = (n < OUTC) ? __ldg(pb + n) : 0.0f;
            float2 e0 = unpack2(acc[0][v]);
            float2 e1 = unpack2(acc[1][v]);
            hB[r0 * XSTR + n] = e0.x + e0.y + b;
            hB[r1 * XSTR + n] = e1.x + e1.y + b;
        }
    }
    __syncthreads();

    // ---- Trilinear combine over 8 corners, write output ----
    if (tid < OUTC * PTS) {
        int col = tid >> 2, pt = tid & 3;
        float a = 0.0f;
#pragma unroll
        for (int c8 = 0; c8 < 8; ++c8) {
            int row = pt * 8 + c8;
            a = fmaf(w8S[row], hB[row * XSTR + col], a);
        }
        out[col * QTOT + pbase + pt] = a;
    }
}

extern "C" void kernel_launch(void* const* d_in, const int* in_sizes, int n_in,
                              void* d_out, int out_size) {
    const float* ctxv = (const float*)d_in[0];   // context_v (1,96,32,32,32)
    const float* ext  = (const float*)d_in[1];   // context_spatial_extent (1,3,32,32,32)
    const float* qvs  = (const float*)d_in[2];   // query_vox_size (1,3)
    const float* qc   = (const float*)d_in[3];   // query_coord (1,3,48,48,48)
    const float* w00 = (const float*)d_in[4];
    const float* b00 = (const float*)d_in[5];
    const float* w01 = (const float*)d_in[6];
    const float* b01 = (const float*)d_in[7];
    const float* w02 = (const float*)d_in[8];
    const float* b02 = (const float*)d_in[9];
    const float* w10 = (const float*)d_in[10];
    const float* b10 = (const float*)d_in[11];
    const float* w11 = (const float*)d_in[12];
    const float* b11 = (const float*)d_in[13];
    const float* w12 = (const float*)d_in[14];
    const float* b12 = (const float*)d_in[15];
    const float* pw  = (const float*)d_in[16];
    const float* pb  = (const float*)d_in[17];
    float* out = (float*)d_out;

    cudaFuncSetAttribute(main_kernel, cudaFuncAttributeMaxDynamicSharedMemorySize, SMEM_BYTES);

    init_min_kernel<<<1, 32>>>();
    min_kernel<<<QTOT / 256, 256>>>(ext, qc);
    main_kernel<<<QTOT / PTS, THREADS, SMEM_BYTES>>>(
        ctxv, ext, qvs, qc,
        w00, b00, w01, b01, w02, b02,
        w10, b10, w11, b11, w12, b12,
        pw, pb, out);
}

// round 9
// speedup vs baseline: 1.2667x; 1.0002x over previous
#include <cuda_runtime.h>
#include <math.h>

// Problem constants (B=1, CX=CY=CZ=32, QX=QY=QZ=48)
#define QTOT   110592      // 48^3
#define CTXC   96
#define OUTC   45
#define PTS    4           // points per CTA
#define ROWS   32          // PTS * 8 corners
#define XSTR   100         // act row stride (floats), mult of 4
#define CSTR   60          // coord row stride (floats), mult of 4
#define ISTRM  100         // transposed weight i-stride, mid layers (96 padded)
#define ISTR0  164         // transposed weight i-stride, 156-input layers (padded)
#define THREADS 256

// Shared memory layout (floats)
#define OFF_X    0                       // 32*100 = 3200
#define OFF_HA   3200
#define OFF_HB   6400
#define OFF_C    9600                    // 32*60 = 1920
#define OFF_W    11520                   // 96*164 = 15744
#define OFF_W8   27264                   // 32
#define OFF_PT   27296                   // 12
#define OFF_PQ   27308                   // 12
#define OFF_PR   27320                   // 12
#define OFF_MISC 27332                   // qv3 vox3 min3 (+pad)
#define OFF_INT  27344                   // ints: near[12], rowBase[32]
#define SMEM_FLOATS (OFF_INT + 12 + 32)
#define SMEM_BYTES  (SMEM_FLOATS * 4)

typedef unsigned long long u64t;

__device__ unsigned int g_min_enc[3];

__device__ __forceinline__ unsigned fenc(float f) {
    unsigned u = __float_as_uint(f);
    return (u & 0x80000000u) ? ~u : (u | 0x80000000u);
}
__device__ __forceinline__ float fdec(unsigned e) {
    return __uint_as_float((e & 0x80000000u) ? (e ^ 0x80000000u) : ~e);
}
__device__ __forceinline__ float silu(float x) {
    return x * (1.0f / (1.0f + __expf(-x)));
}

// packed f32x2 FMA (FFMA2): both operands are natural 64-bit pairs.
__device__ __forceinline__ void fma2(u64t& d, u64t a, u64t b) {
    asm("fma.rn.f32x2 %0, %1, %2, %0;" : "+l"(d) : "l"(a), "l"(b));
}
__device__ __forceinline__ float2 unpack2(u64t v) {
    unsigned lo, hi;
    asm("mov.b64 {%0, %1}, %2;" : "=r"(lo), "=r"(hi) : "l"(v));
    return make_float2(__uint_as_float(lo), __uint_as_float(hi));
}
// 16B shared load directly into two 64-bit regs (zero pack MOVs).
__device__ __forceinline__ void lds2(u64t& a, u64t& b, unsigned addr) {
    asm("ld.shared.v2.u64 {%0, %1}, [%2];" : "=l"(a), "=l"(b) : "r"(addr));
}

__global__ void init_min_kernel() {
    if (threadIdx.x < 3) g_min_enc[threadIdx.x] = 0xFFFFFFFFu;
}

// Global min over raw rel000 (pre-clamp) per dim. Clamp applied later (monotone).
__global__ void min_kernel(const float* __restrict__ ext, const float* __restrict__ qc) {
    int p = blockIdx.x * blockDim.x + threadIdx.x;
    float raw[3] = {1e30f, 1e30f, 1e30f};
    if (p < QTOT) {
        int ni[3];
        float q[3];
#pragma unroll
        for (int d = 0; d < 3; d++) {
            float o = ext[d * 32768];
            float v = fabsf(ext[d * 32768 + 1057] - o);
            q[d] = qc[d * QTOT + p];
            int n = __float2int_rn((q[d] - o) / v);
            ni[d] = min(max(n, 0), 30);
        }
#pragma unroll
        for (int d = 0; d < 3; d++) {
            float cc = ext[d * 32768 + ni[0] * 1024 + ni[1] * 32 + ni[2]];
            raw[d] = cc - q[d];
        }
    }
#pragma unroll
    for (int off = 16; off; off >>= 1) {
#pragma unroll
        for (int d = 0; d < 3; d++)
            raw[d] = fminf(raw[d], __shfl_down_sync(0xffffffffu, raw[d], off));
    }
    if ((threadIdx.x & 31) == 0) {
#pragma unroll
        for (int d = 0; d < 3; d++)
            atomicMin(&g_min_enc[d], fenc(raw[d]));
    }
}

// Matvec partial: 2 rows x 6 neurons per thread, FFMA2 paired along i.
__device__ __forceinline__ void mm_part6(u64t (&acc)[2][6], unsigned aA, unsigned aB,
                                         unsigned wbase, unsigned wstr, int nin) {
#pragma unroll 2
    for (int i = 0; i < nin; i += 4) {
        u64t x0, x1, y0, y1;
        lds2(x0, x1, aA + i * 4);
        lds2(y0, y1, aB + i * 4);
#pragma unroll
        for (int v = 0; v < 6; ++v) {
            u64t w0, w1;
            lds2(w0, w1, wbase + v * wstr + i * 4);
            fma2(acc[0][v], x0, w0); fma2(acc[0][v], x1, w1);
            fma2(acc[1][v], y0, w0); fma2(acc[1][v], y1, w1);
        }
    }
}

// Staging (register-carried): global [96][96] row-major -> smem wT[n][i] transposed.
__device__ __forceinline__ void stage_load_96(float4 (&st)[9], const float* __restrict__ src, int tid) {
#pragma unroll
    for (int j = 0; j < 9; ++j) {
        int c = tid + j * 256;
        int i4 = c / 96, n = c - i4 * 96;
        const float* s = src + i4 * 4 * 96 + n;
        st[j].x = s[0]; st[j].y = s[96]; st[j].z = s[192]; st[j].w = s[288];
    }
}
__device__ __forceinline__ void stage_store_96(const float4 (&st)[9], float* wT, int tid) {
#pragma unroll
    for (int j = 0; j < 9; ++j) {
        int c = tid + j * 256;
        int i4 = c / 96, n = c - i4 * 96;
        *(float4*)(wT + n * ISTRM + i4 * 4) = st[j];
    }
}
// 156-input layer: [156][96] row-major -> wT[n][i], stride ISTR0.
__device__ __forceinline__ void stage_load_156(float4 (&st)[15], const float* __restrict__ src, int tid) {
#pragma unroll
    for (int j = 0; j < 15; ++j) {
        int c = tid + j * 256;
        float4 t = make_float4(0.f, 0.f, 0.f, 0.f);
        if (c < 3744) {
            int i4 = c / 96, n = c - i4 * 96;
            const float* s = src + i4 * 4 * 96 + n;
            t.x = s[0]; t.y = s[96]; t.z = s[192]; t.w = s[288];
        }
        st[j] = t;
    }
}
__device__ __forceinline__ void stage_store_156(const float4 (&st)[15], float* wT, int tid) {
#pragma unroll
    for (int j = 0; j < 15; ++j) {
        int c = tid + j * 256;
        if (c < 3744) {
            int i4 = c / 96, n = c - i4 * 96;
            *(float4*)(wT + n * ISTR0 + i4 * 4) = st[j];
        }
    }
}
// post: pw [96][45] -> wT[48][ISTRM] zero-padded
__device__ __forceinline__ void stage_load_post(float4 (&st)[5], const float* __restrict__ pw, int tid) {
#pragma unroll
    for (int j = 0; j < 5; ++j) {
        int c = tid + j * 256;
        float4 t = make_float4(0.f, 0.f, 0.f, 0.f);
        if (c < 1152) {
            int i4 = c / 48, n = c - i4 * 48;
            if (n < OUTC) {
                t.x = pw[(i4 * 4 + 0) * OUTC + n];
                t.y = pw[(i4 * 4 + 1) * OUTC + n];
                t.z = pw[(i4 * 4 + 2) * OUTC + n];
                t.w = pw[(i4 * 4 + 3) * OUTC + n];
            }
        }
        st[j] = t;
    }
}
__device__ __forceinline__ void stage_store_post(const float4 (&st)[5], float* wT, int tid) {
#pragma unroll
    for (int j = 0; j < 5; ++j) {
        int c = tid + j * 256;
        if (c < 1152) {
            int i4 = c / 48, n = c - i4 * 48;
            *(float4*)(wT + n * ISTRM + i4 * 4) = st[j];
        }
    }
}

__global__ __launch_bounds__(THREADS, 2) void main_kernel(
    const float* __restrict__ ctxv, const float* __restrict__ ext,
    const float* __restrict__ qvs, const float* __restrict__ qc,
    const float* __restrict__ w00, const float* __restrict__ b00,
    const float* __restrict__ w01, const float* __restrict__ b01,
    const float* __restrict__ w02, const float* __restrict__ b02,
    const float* __restrict__ w10, const float* __restrict__ b10,
    const float* __restrict__ w11, const float* __restrict__ b11,
    const float* __restrict__ w12, const float* __restrict__ b12,
    const float* __restrict__ pw, const float* __restrict__ pb,
    float* __restrict__ out) {
    extern __shared__ float sm[];
    float* xS = sm + OFF_X;
    float* hA = sm + OFF_HA;
    float* hB = sm + OFF_HB;
    float* coordS = sm + OFF_C;
    float* wS = sm + OFF_W;
    float* w8S = sm + OFF_W8;
    float* ptT = sm + OFF_PT;
    float* ptQ = sm + OFF_PQ;
    float* ptR = sm + OFF_PR;
    float* qvS = sm + OFF_MISC;
    float* voxS = qvS + 3;
    float* minS = voxS + 3;
    int* nearS = (int*)(sm + OFF_INT);
    int* rowBaseS = nearS + 12;

    const int tid = threadIdx.x;
    const int pbase = blockIdx.x * PTS;
    const unsigned smb = (unsigned)__cvta_generic_to_shared(sm);
    const unsigned xA = smb + OFF_X * 4;
    const unsigned hAA = smb + OFF_HA * 4;
    const unsigned hBA = smb + OFF_HB * 4;
    const unsigned cAbase = smb + OFF_C * 4;
    const unsigned wA = smb + OFF_W * 4;

    const int lane = tid & 31;
    const int warp = tid >> 5;
    const int nq = lane & 1;
    const int rq = lane >> 1;       // 0..15
    const int r0 = rq, r1 = rq + 16;
    const int n0 = warp * 12 + nq * 6;   // 6 neurons n0..n0+5

    // ---- Stage layer-0 weights (transposed) into regs early; LDG latency
    // overlaps the feature-setup work below ----
    float4 st0[15];
    stage_load_156(st0, w00, tid);

    // ---- Region 1 ----
    if (tid < 3) {
        float o = ext[tid * 32768];
        qvS[tid] = qvs[tid];
        voxS[tid] = fabsf(ext[tid * 32768 + 1057] - o);
        minS[tid] = fdec(g_min_enc[tid]);
    }
    if (tid < 12) {
        int pt = tid / 3, d = tid - pt * 3;
        float o = ext[d * 32768];
        float v = fabsf(ext[d * 32768 + 1057] - o);
        float q = qc[d * QTOT + pbase + pt];
        int n = __float2int_rn((q - o) / v);
        nearS[tid] = min(max(n, 0), 30);
        ptQ[tid] = q;
    }
    __syncthreads();

    // ---- Region 2: raw rel000, trilinear t, per-row gather base ----
    if (tid < 12) {
        int pt = tid / 3, d = tid - pt * 3;
        float cc = ext[d * 32768 + nearS[pt * 3] * 1024 + nearS[pt * 3 + 1] * 32 + nearS[pt * 3 + 2]];
        float raw = cc - ptQ[tid];
        ptR[tid] = raw;
        float v = voxS[d];
        float clampc = fmaf(v, -0.5f, 1e-7f);
        float rel0 = fmaxf(raw, clampc);
        float g = fminf(fmaxf((rel0 - 0.5f) * 2.0f, -1.0f + 1e-7f), 1.0f - 1e-7f);
        ptT[tid] = (g + 1.0f) * 0.5f;
    }
    if (tid < ROWS) {
        int pt = tid >> 3, cn = tid & 7;
        int ix = nearS[pt * 3 + 0] + ((cn >> 2) & 1);
        int iy = nearS[pt * 3 + 1] + ((cn >> 1) & 1);
        int iz = nearS[pt * 3 + 2] + (cn & 1);
        rowBaseS[tid] = ix * 1024 + iy * 32 + iz;
    }
    __syncthreads();

    // ---- Region 3: trilinear weights, coord features, context gather ----
    if (tid < ROWS) {
        int pt = tid >> 3, cn = tid & 7;
        float wi = ((cn >> 2) & 1) ? ptT[pt * 3 + 2] : 1.0f - ptT[pt * 3 + 2];
        float wj = ((cn >> 1) & 1) ? ptT[pt * 3 + 1] : 1.0f - ptT[pt * 3 + 1];
        float wk = (cn & 1) ? ptT[pt * 3 + 0] : 1.0f - ptT[pt * 3 + 0];
        w8S[tid] = wi * wj * wk;
    }
    if (tid < ROWS * 3) {
        int row = tid / 3, d = tid - row * 3;
        int pt = row >> 3, cn = row & 7;
        int off = (d == 0) ? ((cn >> 2) & 1) : (d == 1) ? ((cn >> 1) & 1) : (cn & 1);
        float v = voxS[d];
        float clampc = fmaf(v, -0.5f, 1e-7f);
        float raw = ptR[pt * 3 + d] + (float)off * v;
        float rel = fmaxf(raw, clampc);
        float rmin = fmaxf(minS[d] + (float)off * v, clampc);
        float rn = (rel - rmin) / (1.5f * v);
        float cc = ext[d * 32768 + rowBaseS[row]];
        float* cf = coordS + row * CSTR;
        cf[0 + d] = qvS[d];
        cf[3 + d] = cc;
        cf[6 + d] = ptQ[pt * 3 + d];
        cf[9 + d] = rn;
        const float TWO_PI = 6.2831853071795864769f;
#pragma unroll
        for (int f = 0; f < 8; ++f) {
            float fr = exp2f((float)f * 0.29024101186092026f);  // 5^(f/8)
            float ang = TWO_PI * rn * fr;
            cf[12 + d * 16 + f] = sinf(ang);
            cf[12 + d * 16 + 8 + f] = cosf(ang);
        }
    }
    // context gather: warp sweeps rows for fixed channel (corner pairs share sectors)
    for (int idx = tid; idx < ROWS * CTXC; idx += THREADS) {
        int row = idx & 31, c = idx >> 5;
        xS[row * XSTR + c] = ctxv[c * 32768 + rowBaseS[row]];
    }
    // store layer-0 transposed weights
    stage_store_156(st0, wS, tid);
    __syncthreads();

    // ---- MLP: 2 skip blocks of (156->96, 96->96, 96->96), all silu ----
    const float* WPn[5] = {w01, w02, w10, w11, w12};  // source of layer lidx+1
    const float* BP[6] = {b00, b01, b02, b10, b11, b12};

#pragma unroll 1
    for (int blk = 0; blk < 2; ++blk) {
#pragma unroll 1
        for (int l = 0; l < 3; ++l) {
            int lidx = blk * 3 + l;
            // prefetch next weights into regs (hidden behind matvec).
            // lidx==2's successor (w10) is 156-wide: handled synchronously below.
            float4 stm[9];
            float4 stp[5];
            bool midnext = (lidx == 0 || lidx == 1 || lidx == 3 || lidx == 4);
            bool postnext = (lidx == 5);
            if (midnext) stage_load_96(stm, WPn[lidx], tid);
            else if (postnext) stage_load_post(stp, pw, tid);

            unsigned inA = (l == 0) ? xA : ((l == 1) ? hAA : hBA);
            float* outP = (l == 1) ? hB : hA;
            unsigned wstr = (l == 0) ? (ISTR0 * 4) : (ISTRM * 4);
            unsigned wbase = wA + n0 * wstr;

            u64t acc[2][6];
#pragma unroll
            for (int v = 0; v < 6; ++v) { acc[0][v] = 0ull; acc[1][v] = 0ull; }

            mm_part6(acc, inA + r0 * (XSTR * 4), inA + r1 * (XSTR * 4), wbase, wstr, CTXC);
            if (l == 0)
                mm_part6(acc, cAbase + r0 * (CSTR * 4), cAbase + r1 * (CSTR * 4),
                         wbase + 96 * 4, wstr, CSTR);

            const float* bp = BP[lidx];
#pragma unroll
            for (int v = 0; v < 6; ++v) {
                float b = __ldg(bp + n0 + v);
                float2 e0 = unpack2(acc[0][v]);
                float2 e1 = unpack2(acc[1][v]);
                outP[r0 * XSTR + n0 + v] = silu(e0.x + e0.y + b);
                outP[r1 * XSTR + n0 + v] = silu(e1.x + e1.y + b);
            }
            __syncthreads();   // wS free + outP ready
            if (midnext) {
                stage_store_96(stm, wS, tid);
            } else if (postnext) {
                stage_store_post(stp, wS, tid);
            } else {
                // lidx == 2: synchronous full stage of the 156-wide w10
                float4 stb[15];
                stage_load_156(stb, w10, tid);
                stage_store_156(stb, wS, tid);
            }
            __syncthreads();   // new weights visible
        }

        // Skip add: x += h (h in hA after layer 2)
        for (int idx = tid; idx < ROWS * CTXC; idx += THREADS) {
            int row = idx / CTXC, c = idx - row * CTXC;
            xS[row * XSTR + c] += hA[row * XSTR + c];
        }
        __syncthreads();
    }

    // ---- Post layer: 96 -> 45 (48-padded), no activation ----
    {
        const int n0p = warp * 6 + nq * 3;   // 3 neurons
        u64t acc[2][3];
#pragma unroll
        for (int v = 0; v < 3; ++v) { acc[0][v] = 0ull; acc[1][v] = 0ull; }
        unsigned wbase = wA + n0p * (ISTRM * 4);
#pragma unroll 2
        for (int i = 0; i < CTXC; i += 4) {
            u64t x0, x1, y0, y1;
            lds2(x0, x1, xA + r0 * (XSTR * 4) + i * 4);
            lds2(y0, y1, xA + r1 * (XSTR * 4) + i * 4);
#pragma unroll
            for (int v = 0; v < 3; ++v) {
                u64t w0, w1;
                lds2(w0, w1, wbase + v * (ISTRM * 4) + i * 4);
                fma2(acc[0][v], x0, w0); fma2(acc[0][v], x1, w1);
                fma2(acc[1][v], y0, w0); fma2(acc[1][v], y1, w1);
            }
        }
#pragma unroll
        for (int v = 0; v < 3; ++v) {
            int n = n0p + v;
            float b = (n < OUTC) ? __ldg(pb + n) : 0.0f;
            float2 e0 = unpack2(acc[0][v]);
            float2 e1 = unpack2(acc[1][v]);
            hB[r0 * XSTR + n] = e0.x + e0.y + b;
            hB[r1 * XSTR + n] = e1.x + e1.y + b;
        }
    }
    __syncthreads();

    // ---- Trilinear combine over 8 corners, write output ----
    if (tid < OUTC * PTS) {
        int col = tid >> 2, pt = tid & 3;
        float a = 0.0f;
#pragma unroll
        for (int c8 = 0; c8 < 8; ++c8) {
            int row = pt * 8 + c8;
            a = fmaf(w8S[row], hB[row * XSTR + col], a);
        }
        out[col * QTOT + pbase + pt] = a;
    }
}

extern "C" void kernel_launch(void* const* d_in, const int* in_sizes, int n_in,
                              void* d_out, int out_size) {
    const float* ctxv = (const float*)d_in[0];   // context_v (1,96,32,32,32)
    const float* ext  = (const float*)d_in[1];   // context_spatial_extent (1,3,32,32,32)
    const float* qvs  = (const float*)d_in[2];   // query_vox_size (1,3)
    const float* qc   = (const float*)d_in[3];   // query_coord (1,3,48,48,48)
    const float* w00 = (const float*)d_in[4];
    const float* b00 = (const float*)d_in[5];
    const float* w01 = (const float*)d_in[6];
    const float* b01 = (const float*)d_in[7];
    const float* w02 = (const float*)d_in[8];
    const float* b02 = (const float*)d_in[9];
    const float* w10 = (const float*)d_in[10];
    const float* b10 = (const float*)d_in[11];
    const float* w11 = (const float*)d_in[12];
    const float* b11 = (const float*)d_in[13];
    const float* w12 = (const float*)d_in[14];
    const float* b12 = (const float*)d_in[15];
    const float* pw  = (const float*)d_in[16];
    const float* pb  = (const float*)d_in[17];
    float* out = (float*)d_out;

    cudaFuncSetAttribute(main_kernel, cudaFuncAttributeMaxDynamicSharedMemorySize, SMEM_BYTES);

    init_min_kernel<<<1, 32>>>();
    min_kernel<<<QTOT / 256, 256>>>(ext, qc);
    main_kernel<<<QTOT / PTS, THREADS, SMEM_BYTES>>>(
        ctxv, ext, qvs, qc,
        w00, b00, w01, b01, w02, b02,
        w10, b10, w11, b11, w12, b12,
        pw, pb, out);
}

// round 12
// speedup vs baseline: 1.3254x; 1.0464x over previous
#include <cuda_runtime.h>
#include <cuda_bf16.h>
#include <stdint.h>
#include <math.h>

#define QTOT 110592
#define OUTC 45
#define PTSB 16
#define TROWS 128
#define THREADS 256

#define ASTR 168            // act plane stride (bf16 elems), 336B: conflict-free ldmatrix
#define WSTR 104            // weight plane stride (bf16 elems), 208B
#define XSTRF 100           // fp32 skip-state stride

// smem byte offsets
#define SM_AH 0                          // bf16 [128][168] hi  43008
#define SM_AL 43008                      // bf16 [128][168] lo  43008
#define SM_WH 86016                      // bf16 [160][104] hi  33280
#define SM_WL 119296                     // bf16 [160][104] lo  33280
#define SM_XS 152576                     // fp32 [128][100]     51200
#define SM_RB 203776                     // int[128]
#define SM_W8 204288                     // float[128]
#define SM_PTQ 204800                    // float[48]
#define SM_PTR 204992                    // float[48]
#define SM_PTT 205184                    // float[48]
#define SM_NEAR 205376                   // int[48]
#define SM_MISC 205568                   // qv[3]@0 vox[3]@12 min[3]@24
#define SM_PB 205616                     // float[192]: double-buffered 96-bias
#define SMEM_TOTAL 206384

__device__ unsigned int g_min_enc[3];

__device__ __forceinline__ unsigned fenc(float f) {
    unsigned u = __float_as_uint(f);
    return (u & 0x80000000u) ? ~u : (u | 0x80000000u);
}
__device__ __forceinline__ float fdec(unsigned e) {
    return __uint_as_float((e & 0x80000000u) ? (e ^ 0x80000000u) : ~e);
}
__device__ __forceinline__ float silu(float x) {
    return x * (1.0f / (1.0f + __expf(-x)));
}
__device__ __forceinline__ void split2(float a, float b, uint32_t& hw, uint32_t& lw) {
    __nv_bfloat16 ha = __float2bfloat16(a), hb = __float2bfloat16(b);
    __nv_bfloat16 la = __float2bfloat16(a - __bfloat162float(ha));
    __nv_bfloat16 lb = __float2bfloat16(b - __bfloat162float(hb));
    hw = (uint32_t)__bfloat16_as_ushort(ha) | ((uint32_t)__bfloat16_as_ushort(hb) << 16);
    lw = (uint32_t)__bfloat16_as_ushort(la) | ((uint32_t)__bfloat16_as_ushort(lb) << 16);
}

// ---- baseline-PTX tensor ops (sm_80-era; no 'a' target required) ----
__device__ __forceinline__ void ldsm4(uint32_t* r, uint32_t a) {
    asm volatile("ldmatrix.sync.aligned.m8n8.x4.shared.b16 {%0,%1,%2,%3}, [%4];"
                 : "=r"(r[0]), "=r"(r[1]), "=r"(r[2]), "=r"(r[3]) : "r"(a));
}
__device__ __forceinline__ void ldsm2t(uint32_t* r, uint32_t a) {
    asm volatile("ldmatrix.sync.aligned.m8n8.x2.trans.shared.b16 {%0,%1}, [%2];"
                 : "=r"(r[0]), "=r"(r[1]) : "r"(a));
}
__device__ __forceinline__ void mmabf(float* d, const uint32_t* a, const uint32_t* b) {
    asm volatile(
        "mma.sync.aligned.m16n8k16.row.col.f32.bf16.bf16.f32 "
        "{%0,%1,%2,%3}, {%4,%5,%6,%7}, {%8,%9}, {%0,%1,%2,%3};"
        : "+f"(d[0]), "+f"(d[1]), "+f"(d[2]), "+f"(d[3])
        : "r"(a[0]), "r"(a[1]), "r"(a[2]), "r"(a[3]), "r"(b[0]), "r"(b[1]));
}

__global__ void init_min_kernel() {
    if (threadIdx.x < 3) g_min_enc[threadIdx.x] = 0xFFFFFFFFu;
}
__global__ void min_kernel(const float* __restrict__ ext, const float* __restrict__ qc) {
    int p = blockIdx.x * blockDim.x + threadIdx.x;
    float raw[3] = {1e30f, 1e30f, 1e30f};
    if (p < QTOT) {
        int ni[3]; float q[3];
#pragma unroll
        for (int d = 0; d < 3; d++) {
            float o = ext[d * 32768];
            float v = fabsf(ext[d * 32768 + 1057] - o);
            q[d] = qc[d * QTOT + p];
            int n = __float2int_rn((q[d] - o) / v);
            ni[d] = min(max(n, 0), 30);
        }
#pragma unroll
        for (int d = 0; d < 3; d++)
            raw[d] = ext[d * 32768 + ni[0] * 1024 + ni[1] * 32 + ni[2]] - q[d];
    }
#pragma unroll
    for (int off = 16; off; off >>= 1)
#pragma unroll
        for (int d = 0; d < 3; d++)
            raw[d] = fminf(raw[d], __shfl_down_sync(0xffffffffu, raw[d], off));
    if ((threadIdx.x & 31) == 0)
#pragma unroll
        for (int d = 0; d < 3; d++)
            atomicMin(&g_min_enc[d], fenc(raw[d]));
}

// Stage W [Kreal][ldw] fp32 row-major -> bf16 hi/lo planes [Kpad][WSTR], zero-padded.
__device__ void stage_w(const float* __restrict__ W, int ldw, int nval,
                        int Kreal, int Kpad, int ntiles, char* smc, int tid) {
    uint32_t* whi = (uint32_t*)(smc + SM_WH);
    uint32_t* wlo = (uint32_t*)(smc + SM_WL);
    int npairs = ntiles * 4;
    int tasks = Kpad * npairs;
    for (int t = tid; t < tasks; t += THREADS) {
        int k = t / npairs, m = t - k * npairs;
        int n = m * 2;
        float v0 = (k < Kreal && n < nval) ? W[k * ldw + n] : 0.0f;
        float v1 = (k < Kreal && n + 1 < nval) ? W[k * ldw + n + 1] : 0.0f;
        uint32_t hw, lw; split2(v0, v1, hw, lw);
        int idx = (k * WSTR + n) >> 1;
        whi[idx] = hw;
        wlo[idx] = lw;
    }
}

// One GEMM round: acc += A[128 x 16*ksteps] * W  (bf16 x3 split, fp32 accum)
template <int NT>
__device__ __forceinline__ void do_round(float (&acc)[12][4], int ksteps,
                                         uint32_t aH, uint32_t aL,
                                         uint32_t wH, uint32_t wL) {
#pragma unroll 1
    for (int k = 0; k < ksteps; k++) {
        uint32_t ah[4], al[4];
        ldsm4(ah, aH + k * 32);
        ldsm4(al, aL + k * 32);
        uint32_t wkH = wH + k * 16 * (WSTR * 2);
        uint32_t wkL = wL + k * 16 * (WSTR * 2);
#pragma unroll
        for (int t = 0; t < NT; t++) {
            uint32_t bh[2], bl[2];
            ldsm2t(bh, wkH + t * 16);
            ldsm2t(bl, wkL + t * 16);
            mmabf(acc[t], ah, bh);
            mmabf(acc[t], ah, bl);
            mmabf(acc[t], al, bh);
        }
    }
}

__global__ __launch_bounds__(THREADS, 1) void main_kernel(
    const float* __restrict__ ctxv, const float* __restrict__ ext,
    const float* __restrict__ qvs, const float* __restrict__ qc,
    const float* __restrict__ w00, const float* __restrict__ b00,
    const float* __restrict__ w01, const float* __restrict__ b01,
    const float* __restrict__ w02, const float* __restrict__ b02,
    const float* __restrict__ w10, const float* __restrict__ b10,
    const float* __restrict__ w11, const float* __restrict__ b11,
    const float* __restrict__ w12, const float* __restrict__ b12,
    const float* __restrict__ pw, const float* __restrict__ pb,
    float* __restrict__ out) {
    extern __shared__ char smc[];
    float* xS    = (float*)(smc + SM_XS);
    int* rowBase = (int*)(smc + SM_RB);
    float* w8S   = (float*)(smc + SM_W8);
    float* ptQ   = (float*)(smc + SM_PTQ);
    float* ptR   = (float*)(smc + SM_PTR);
    float* ptT   = (float*)(smc + SM_PTT);
    int* nearS   = (int*)(smc + SM_NEAR);
    float* qvS   = (float*)(smc + SM_MISC);
    float* voxS  = qvS + 3;
    float* minS  = voxS + 3;
    float* pbF   = (float*)(smc + SM_PB);

    const int tid = threadIdx.x;
    const int lane = tid & 31;
    const int warp = tid >> 5;
    const int pbase = blockIdx.x * PTSB;
    const uint32_t smb = (uint32_t)__cvta_generic_to_shared(smc);

    // ---- feature setup ----
    if (tid < 3) {
        float o = ext[tid * 32768];
        qvS[tid] = qvs[tid];
        voxS[tid] = fabsf(ext[tid * 32768 + 1057] - o);
        minS[tid] = fdec(g_min_enc[tid]);
    }
    if (tid < 48) {
        int pt = tid / 3, d = tid - pt * 3;
        float o = ext[d * 32768];
        float v = fabsf(ext[d * 32768 + 1057] - o);
        float q = qc[d * QTOT + pbase + pt];
        int n = __float2int_rn((q - o) / v);
        nearS[tid] = min(max(n, 0), 30);
        ptQ[tid] = q;
    }
    __syncthreads();
    if (tid < 48) {
        int pt = tid / 3, d = tid - pt * 3;
        float cc = ext[d * 32768 + nearS[pt * 3] * 1024 + nearS[pt * 3 + 1] * 32 + nearS[pt * 3 + 2]];
        float raw = cc - ptQ[tid];
        ptR[tid] = raw;
        float v = voxS[d];
        float clampc = fmaf(v, -0.5f, 1e-7f);
        float rel0 = fmaxf(raw, clampc);
        float g = fminf(fmaxf((rel0 - 0.5f) * 2.0f, -1.0f + 1e-7f), 1.0f - 1e-7f);
        ptT[tid] = (g + 1.0f) * 0.5f;
    }
    if (tid < TROWS) {
        int pt = tid >> 3, cn = tid & 7;
        int ix = nearS[pt * 3 + 0] + ((cn >> 2) & 1);
        int iy = nearS[pt * 3 + 1] + ((cn >> 1) & 1);
        int iz = nearS[pt * 3 + 2] + (cn & 1);
        rowBase[tid] = ix * 1024 + iy * 32 + iz;
    }
    __syncthreads();
    if (tid < TROWS) {
        int pt = tid >> 3, cn = tid & 7;
        float wi = ((cn >> 2) & 1) ? ptT[pt * 3 + 2] : 1.0f - ptT[pt * 3 + 2];
        float wj = ((cn >> 1) & 1) ? ptT[pt * 3 + 1] : 1.0f - ptT[pt * 3 + 1];
        float wk = (cn & 1) ? ptT[pt * 3 + 0] : 1.0f - ptT[pt * 3 + 0];
        w8S[tid] = wi * wj * wk;
    }
    // context gather -> xS (fp32 skip state)
    for (int idx = tid; idx < TROWS * 96; idx += THREADS) {
        int row = idx & 127, c = idx >> 7;
        xS[row * XSTRF + c] = ctxv[c * 32768 + rowBase[row]];
    }
    __syncthreads();

    // ---- initial act fill: cols 0..95 = x, 96..155 = coord feats, 156..159 = 0
    if (tid < TROWS) {
        int row = tid;
        uint32_t* ah = (uint32_t*)(smc + SM_AH);
        uint32_t* al = (uint32_t*)(smc + SM_AL);
        float* xrow = xS + row * XSTRF;
        int base = row * ASTR;
        for (int c = 0; c < 96; c += 2) {
            uint32_t hw, lw; split2(xrow[c], xrow[c + 1], hw, lw);
            ah[(base + c) >> 1] = hw;
            al[(base + c) >> 1] = lw;
        }
        int pt = row >> 3, cn = row & 7;
        float f[64];
        f[60] = f[61] = f[62] = f[63] = 0.f;
        int rb = rowBase[row];
#pragma unroll
        for (int d = 0; d < 3; d++) {
            int off = (d == 0) ? ((cn >> 2) & 1) : (d == 1) ? ((cn >> 1) & 1) : (cn & 1);
            float v = voxS[d];
            float clampc = fmaf(v, -0.5f, 1e-7f);
            float raw = ptR[pt * 3 + d] + (float)off * v;
            float rel = fmaxf(raw, clampc);
            float rmin = fmaxf(minS[d] + (float)off * v, clampc);
            float rn = (rel - rmin) / (1.5f * v);
            f[d] = qvS[d];
            f[3 + d] = ext[d * 32768 + rb];
            f[6 + d] = ptQ[pt * 3 + d];
            f[9 + d] = rn;
            const float TWO_PI = 6.2831853071795864769f;
#pragma unroll
            for (int i = 0; i < 8; i++) {
                float fr = exp2f((float)i * 0.29024101186092026f);  // 5^(i/8)
                float ang = TWO_PI * rn * fr;
                f[12 + d * 16 + i] = sinf(ang);
                f[12 + d * 16 + 8 + i] = cosf(ang);
            }
        }
        for (int c = 0; c < 64; c += 2) {
            uint32_t hw, lw; split2(f[c], f[c + 1], hw, lw);
            ah[(base + 96 + c) >> 1] = hw;
            al[(base + 96 + c) >> 1] = lw;
        }
    }

    // ldmatrix base addresses (bytes)
    const uint32_t aH = smb + SM_AH + ((warp * 16 + (lane & 15)) * ASTR + (lane >> 4) * 8) * 2;
    const uint32_t aL = aH + (SM_AL - SM_AH);
    const uint32_t wHb = smb + SM_WH + ((lane & 15) * WSTR) * 2;
    const uint32_t wLb = wHb + (SM_WL - SM_WH);

    // ---- 7 rounds: L0, L1, L2, L0', L1', L2', post ----
    const float* Wt[7] = {w00, w01, w02, w10, w11, w12, pw};
    const float* Bt[7] = {b00, b01, b02, b10, b11, b12, pb};
    const int Kreal[7] = {156, 96, 96, 156, 96, 96, 96};
    const int Kpad[7]  = {160, 96, 96, 160, 96, 96, 96};
    const int ldw[7]   = {96, 96, 96, 96, 96, 96, OUTC};
    const int nval[7]  = {96, 96, 96, 96, 96, 96, OUTC};
    const int ntil[7]  = {12, 12, 12, 12, 12, 12, 6};

    const int r0 = warp * 16 + (lane >> 2);
    const int r1 = r0 + 8;
    const int cb = (lane & 3) * 2;

#pragma unroll 1
    for (int r = 0; r < 7; r++) {
        __syncthreads();   // all warps done with previous weights + act writes visible
        stage_w(Wt[r], ldw[r], nval[r], Kreal[r], Kpad[r], ntil[r], smc, tid);
        float* bias = pbF + (r & 1) * 96;
        if (tid < 96) bias[tid] = (tid < nval[r]) ? Bt[r][tid] : 0.0f;
        __syncthreads();   // weights visible

        float acc[12][4];
#pragma unroll
        for (int t = 0; t < 12; t++)
            acc[t][0] = acc[t][1] = acc[t][2] = acc[t][3] = 0.0f;

        if (r < 6) {
            do_round<12>(acc, Kpad[r] >> 4, aH, aL, wHb, wLb);
            bool skip = (r % 3 == 2);
            uint32_t* ah = (uint32_t*)(smc + SM_AH);
            uint32_t* al = (uint32_t*)(smc + SM_AL);
#pragma unroll
            for (int t = 0; t < 12; t++) {
                int c = t * 8 + cb;
                float b0 = bias[c], b1 = bias[c + 1];
                float a0 = silu(acc[t][0] + b0), a1 = silu(acc[t][1] + b1);
                float a2 = silu(acc[t][2] + b0), a3 = silu(acc[t][3] + b1);
                if (skip) {
                    a0 += xS[r0 * XSTRF + c];
                    a1 += xS[r0 * XSTRF + c + 1];
                    a2 += xS[r1 * XSTRF + c];
                    a3 += xS[r1 * XSTRF + c + 1];
                    xS[r0 * XSTRF + c] = a0;
                    xS[r0 * XSTRF + c + 1] = a1;
                    xS[r1 * XSTRF + c] = a2;
                    xS[r1 * XSTRF + c + 1] = a3;
                }
                uint32_t hw, lw;
                split2(a0, a1, hw, lw);
                ah[(r0 * ASTR + c) >> 1] = hw;
                al[(r0 * ASTR + c) >> 1] = lw;
                split2(a2, a3, hw, lw);
                ah[(r1 * ASTR + c) >> 1] = hw;
                al[(r1 * ASTR + c) >> 1] = lw;
            }
        } else {
            do_round<6>(acc, 6, aH, aL, wHb, wLb);
            // post epilogue: bias, trilinear weight, corner reduce, write out
            float w8a = w8S[r0], w8b = w8S[r1];
            int ptA = warp * 2, ptB = warp * 2 + 1;
#pragma unroll
            for (int t = 0; t < 6; t++) {
                int c = t * 8 + cb;
                float b0 = bias[c], b1 = bias[c + 1];
                float v0 = (acc[t][0] + b0) * w8a;
                float v1 = (acc[t][1] + b1) * w8a;
                float v2 = (acc[t][2] + b0) * w8b;
                float v3 = (acc[t][3] + b1) * w8b;
#pragma unroll
                for (int m = 4; m <= 16; m <<= 1) {
                    v0 += __shfl_xor_sync(0xffffffffu, v0, m);
                    v1 += __shfl_xor_sync(0xffffffffu, v1, m);
                    v2 += __shfl_xor_sync(0xffffffffu, v2, m);
                    v3 += __shfl_xor_sync(0xffffffffu, v3, m);
                }
                if ((lane >> 2) == 0) {
                    if (c < OUTC) {
                        out[c * QTOT + pbase + ptA] = v0;
                        out[c * QTOT + pbase + ptB] = v2;
                    }
                    if (c + 1 < OUTC) {
                        out[(c + 1) * QTOT + pbase + ptA] = v1;
                        out[(c + 1) * QTOT + pbase + ptB] = v3;
                    }
                }
            }
        }
    }
}

extern "C" void kernel_launch(void* const* d_in, const int* in_sizes, int n_in,
                              void* d_out, int out_size) {
    const float* ctxv = (const float*)d_in[0];
    const float* ext  = (const float*)d_in[1];
    const float* qvs  = (const float*)d_in[2];
    const float* qc   = (const float*)d_in[3];
    const float* w00 = (const float*)d_in[4];
    const float* b00 = (const float*)d_in[5];
    const float* w01 = (const float*)d_in[6];
    const float* b01 = (const float*)d_in[7];
    const float* w02 = (const float*)d_in[8];
    const float* b02 = (const float*)d_in[9];
    const float* w10 = (const float*)d_in[10];
    const float* b10 = (const float*)d_in[11];
    const float* w11 = (const float*)d_in[12];
    const float* b11 = (const float*)d_in[13];
    const float* w12 = (const float*)d_in[14];
    const float* b12 = (const float*)d_in[15];
    const float* pw  = (const float*)d_in[16];
    const float* pb  = (const float*)d_in[17];
    float* out = (float*)d_out;

    cudaFuncSetAttribute(main_kernel, cudaFuncAttributeMaxDynamicSharedMemorySize, SMEM_TOTAL);

    init_min_kernel<<<1, 32>>>();
    min_kernel<<<QTOT / 256, 256>>>(ext, qc);
    main_kernel<<<QTOT / PTSB, THREADS, SMEM_TOTAL>>>(
        ctxv, ext, qvs, qc,
        w00, b00, w01, b01, w02, b02,
        w10, b10, w11, b11, w12, b12,
        pw, pb, out);
}

// round 15
// speedup vs baseline: 1.7113x; 1.2911x over previous
#include <cuda_runtime.h>
#include <cuda_bf16.h>
#include <stdint.h>
#include <math.h>

#define QTOT 110592
#define OUTC 45
#define PTSB 16
#define TROWS 128
#define THREADS 512

#define ASTR 168            // act plane stride (bf16 elems), 336B
#define WSTR 104            // weight plane stride (bf16 elems), 208B
#define XSTRF 100           // fp32 skip-state stride

// smem byte offsets
#define SM_AH 0                          // bf16 [128][168] hi  43008
#define SM_AL 43008                      // bf16 [128][168] lo  43008
#define SM_WH 86016                      // bf16 [160][104] hi  33280
#define SM_WL 119296                     // bf16 [160][104] lo  33280
#define SM_XS 152576                     // fp32 [128][100]     51200
#define SM_RB 203776                     // int[128]
#define SM_W8 204288                     // float[128]
#define SM_PTQ 204800                    // float[48]
#define SM_PTR 204992                    // float[48]
#define SM_PTT 205184                    // float[48]
#define SM_NEAR 205376                   // int[48]
#define SM_MISC 205568                   // qv[3]@0 vox[3]@12 min[3]@24
#define SM_PB 205616                     // float[192]: double-buffered 96-bias
#define SMEM_TOTAL 206384

__device__ unsigned int g_min_enc[3] = {0xFFFFFFFFu, 0xFFFFFFFFu, 0xFFFFFFFFu};
__device__ unsigned int g_done = 0;

__device__ __forceinline__ unsigned fenc(float f) {
    unsigned u = __float_as_uint(f);
    return (u & 0x80000000u) ? ~u : (u | 0x80000000u);
}
__device__ __forceinline__ float fdec(unsigned e) {
    return __uint_as_float((e & 0x80000000u) ? (e ^ 0x80000000u) : ~e);
}
__device__ __forceinline__ float silu(float x) {
    return x * (1.0f / (1.0f + __expf(-x)));
}
__device__ __forceinline__ void split2(float a, float b, uint32_t& hw, uint32_t& lw) {
    __nv_bfloat16 ha = __float2bfloat16(a), hb = __float2bfloat16(b);
    __nv_bfloat16 la = __float2bfloat16(a - __bfloat162float(ha));
    __nv_bfloat16 lb = __float2bfloat16(b - __bfloat162float(hb));
    hw = (uint32_t)__bfloat16_as_ushort(ha) | ((uint32_t)__bfloat16_as_ushort(hb) << 16);
    lw = (uint32_t)__bfloat16_as_ushort(la) | ((uint32_t)__bfloat16_as_ushort(lb) << 16);
}

// ---- baseline-PTX tensor ops (sm_80-era; no 'a' target required) ----
__device__ __forceinline__ void ldsm4(uint32_t* r, uint32_t a) {
    asm volatile("ldmatrix.sync.aligned.m8n8.x4.shared.b16 {%0,%1,%2,%3}, [%4];"
                 : "=r"(r[0]), "=r"(r[1]), "=r"(r[2]), "=r"(r[3]) : "r"(a));
}
__device__ __forceinline__ void ldsm2t(uint32_t* r, uint32_t a) {
    asm volatile("ldmatrix.sync.aligned.m8n8.x2.trans.shared.b16 {%0,%1}, [%2];"
                 : "=r"(r[0]), "=r"(r[1]) : "r"(a));
}
__device__ __forceinline__ void mmabf(float* d, const uint32_t* a, const uint32_t* b) {
    asm volatile(
        "mma.sync.aligned.m16n8k16.row.col.f32.bf16.bf16.f32 "
        "{%0,%1,%2,%3}, {%4,%5,%6,%7}, {%8,%9}, {%0,%1,%2,%3};"
        : "+f"(d[0]), "+f"(d[1]), "+f"(d[2]), "+f"(d[3])
        : "r"(a[0]), "r"(a[1]), "r"(a[2]), "r"(a[3]), "r"(b[0]), "r"(b[1]));
}
// Named barrier for one 2-warp row-pair (ids 1..8, 64 threads).
__device__ __forceinline__ void pair_bar(int mw) {
    asm volatile("bar.sync %0, %1;" :: "r"(mw + 1), "r"(64) : "memory");
}

__global__ void min_kernel(const float* __restrict__ ext, const float* __restrict__ qc) {
    int p = blockIdx.x * blockDim.x + threadIdx.x;
    float raw[3] = {1e30f, 1e30f, 1e30f};
    if (p < QTOT) {
        int ni[3]; float q[3];
#pragma unroll
        for (int d = 0; d < 3; d++) {
            float o = ext[d * 32768];
            float v = fabsf(ext[d * 32768 + 1057] - o);
            q[d] = qc[d * QTOT + p];
            int n = __float2int_rn((q[d] - o) / v);
            ni[d] = min(max(n, 0), 30);
        }
#pragma unroll
        for (int d = 0; d < 3; d++)
            raw[d] = ext[d * 32768 + ni[0] * 1024 + ni[1] * 32 + ni[2]] - q[d];
    }
#pragma unroll
    for (int off = 16; off; off >>= 1)
#pragma unroll
        for (int d = 0; d < 3; d++)
            raw[d] = fminf(raw[d], __shfl_down_sync(0xffffffffu, raw[d], off));
    if ((threadIdx.x & 31) == 0)
#pragma unroll
        for (int d = 0; d < 3; d++)
            atomicMin(&g_min_enc[d], fenc(raw[d]));
}

// LDG phase of weight staging: round weights -> float2 regs.
__device__ __forceinline__ void ldg_w(const float* __restrict__ W, int ldw, int nval,
                                      int Kreal, int Kpad, int npairs,
                                      float2* pf, int tid) {
    int tasks = Kpad * npairs;
    int cnt = 0;
    for (int t = tid; t < tasks; t += THREADS) {
        int k = t / npairs, m = t - k * npairs, n = m * 2;
        float v0 = (k < Kreal && n < nval) ? W[k * ldw + n] : 0.0f;
        float v1 = (k < Kreal && n + 1 < nval) ? W[k * ldw + n + 1] : 0.0f;
        pf[cnt++] = make_float2(v0, v1);
    }
}
// STS phase: regs -> bf16 hi/lo planes [Kpad][WSTR].
__device__ __forceinline__ void sts_w(int Kpad, int npairs, const float2* pf,
                                      char* smc, int tid) {
    uint32_t* whi = (uint32_t*)(smc + SM_WH);
    uint32_t* wlo = (uint32_t*)(smc + SM_WL);
    int tasks = Kpad * npairs;
    int cnt = 0;
    for (int t = tid; t < tasks; t += THREADS) {
        int k = t / npairs, m = t - k * npairs, n = m * 2;
        uint32_t hw, lw; split2(pf[cnt].x, pf[cnt].y, hw, lw);
        cnt++;
        int idx = (k * WSTR + n) >> 1;
        whi[idx] = hw;
        wlo[idx] = lw;
    }
}

// One GEMM round per warp: acc += A[16 rows x 16*ksteps] * W[NT tiles]
template <int NT>
__device__ __forceinline__ void do_round(float (&acc)[NT][4], int ksteps,
                                         uint32_t aH, uint32_t aL,
                                         uint32_t wH, uint32_t wL) {
#pragma unroll 1
    for (int k = 0; k < ksteps; k++) {
        uint32_t ah[4], al[4];
        ldsm4(ah, aH + k * 32);
        ldsm4(al, aL + k * 32);
        uint32_t wkH = wH + k * 16 * (WSTR * 2);
        uint32_t wkL = wL + k * 16 * (WSTR * 2);
#pragma unroll
        for (int t = 0; t < NT; t++) {
            uint32_t bh[2], bl[2];
            ldsm2t(bh, wkH + t * 16);
            ldsm2t(bl, wkL + t * 16);
            mmabf(acc[t], ah, bh);
            mmabf(acc[t], ah, bl);
            mmabf(acc[t], al, bh);
        }
    }
}

__global__ __launch_bounds__(THREADS, 1) void main_kernel(
    const float* __restrict__ ctxv, const float* __restrict__ ext,
    const float* __restrict__ qvs, const float* __restrict__ qc,
    const float* __restrict__ w00, const float* __restrict__ b00,
    const float* __restrict__ w01, const float* __restrict__ b01,
    const float* __restrict__ w02, const float* __restrict__ b02,
    const float* __restrict__ w10, const float* __restrict__ b10,
    const float* __restrict__ w11, const float* __restrict__ b11,
    const float* __restrict__ w12, const float* __restrict__ b12,
    const float* __restrict__ pw, const float* __restrict__ pb,
    float* __restrict__ out) {
    extern __shared__ char smc[];
    float* xS    = (float*)(smc + SM_XS);
    int* rowBase = (int*)(smc + SM_RB);
    float* w8S   = (float*)(smc + SM_W8);
    float* ptQ   = (float*)(smc + SM_PTQ);
    float* ptR   = (float*)(smc + SM_PTR);
    float* ptT   = (float*)(smc + SM_PTT);
    int* nearS   = (int*)(smc + SM_NEAR);
    float* qvS   = (float*)(smc + SM_MISC);
    float* voxS  = qvS + 3;
    float* minS  = voxS + 3;
    float* pbF   = (float*)(smc + SM_PB);

    const int tid = threadIdx.x;
    const int lane = tid & 31;
    const int warp = tid >> 5;
    const int mw = warp >> 1;      // 0..7: 16-row slice
    const int nw = warp & 1;       // 0..1: N half
    const int pbase = blockIdx.x * PTSB;
    const uint32_t smb = (uint32_t)__cvta_generic_to_shared(smc);

    // ---- feature setup ----
    if (tid < 3) {
        float o = ext[tid * 32768];
        qvS[tid] = qvs[tid];
        voxS[tid] = fabsf(ext[tid * 32768 + 1057] - o);
        minS[tid] = fdec(g_min_enc[tid]);
    }
    if (tid < 48) {
        int pt = tid / 3, d = tid - pt * 3;
        float o = ext[d * 32768];
        float v = fabsf(ext[d * 32768 + 1057] - o);
        float q = qc[d * QTOT + pbase + pt];
        int n = __float2int_rn((q - o) / v);
        nearS[tid] = min(max(n, 0), 30);
        ptQ[tid] = q;
    }
    __syncthreads();
    if (tid < 48) {
        int pt = tid / 3, d = tid - pt * 3;
        float cc = ext[d * 32768 + nearS[pt * 3] * 1024 + nearS[pt * 3 + 1] * 32 + nearS[pt * 3 + 2]];
        float raw = cc - ptQ[tid];
        ptR[tid] = raw;
        float v = voxS[d];
        float clampc = fmaf(v, -0.5f, 1e-7f);
        float rel0 = fmaxf(raw, clampc);
        float g = fminf(fmaxf((rel0 - 0.5f) * 2.0f, -1.0f + 1e-7f), 1.0f - 1e-7f);
        ptT[tid] = (g + 1.0f) * 0.5f;
    }
    if (tid < TROWS) {
        int pt = tid >> 3, cn = tid & 7;
        int ix = nearS[pt * 3 + 0] + ((cn >> 2) & 1);
        int iy = nearS[pt * 3 + 1] + ((cn >> 1) & 1);
        int iz = nearS[pt * 3 + 2] + (cn & 1);
        rowBase[tid] = ix * 1024 + iy * 32 + iz;
    }
    __syncthreads();
    if (tid < TROWS) {
        int pt = tid >> 3, cn = tid & 7;
        float wi = ((cn >> 2) & 1) ? ptT[pt * 3 + 2] : 1.0f - ptT[pt * 3 + 2];
        float wj = ((cn >> 1) & 1) ? ptT[pt * 3 + 1] : 1.0f - ptT[pt * 3 + 1];
        float wk = (cn & 1) ? ptT[pt * 3 + 0] : 1.0f - ptT[pt * 3 + 0];
        w8S[tid] = wi * wj * wk;
    }
    // context gather -> xS (fp32 skip state)
    for (int idx = tid; idx < TROWS * 96; idx += THREADS) {
        int row = idx & 127, c = idx >> 7;
        xS[row * XSTRF + c] = ctxv[c * 32768 + rowBase[row]];
    }
    __syncthreads();

    // ---- initial act fill: cols 0..95 = x, 96..155 = coord feats, 156..159 = 0
    if (tid < TROWS) {
        int row = tid;
        uint32_t* ah = (uint32_t*)(smc + SM_AH);
        uint32_t* al = (uint32_t*)(smc + SM_AL);
        float* xrow = xS + row * XSTRF;
        int base = row * ASTR;
        for (int c = 0; c < 96; c += 2) {
            uint32_t hw, lw; split2(xrow[c], xrow[c + 1], hw, lw);
            ah[(base + c) >> 1] = hw;
            al[(base + c) >> 1] = lw;
        }
        int pt = row >> 3, cn = row & 7;
        float f[64];
        f[60] = f[61] = f[62] = f[63] = 0.f;
        int rb = rowBase[row];
#pragma unroll
        for (int d = 0; d < 3; d++) {
            int off = (d == 0) ? ((cn >> 2) & 1) : (d == 1) ? ((cn >> 1) & 1) : (cn & 1);
            float v = voxS[d];
            float clampc = fmaf(v, -0.5f, 1e-7f);
            float raw = ptR[pt * 3 + d] + (float)off * v;
            float rel = fmaxf(raw, clampc);
            float rmin = fmaxf(minS[d] + (float)off * v, clampc);
            float rn = (rel - rmin) / (1.5f * v);
            f[d] = qvS[d];
            f[3 + d] = ext[d * 32768 + rb];
            f[6 + d] = ptQ[pt * 3 + d];
            f[9 + d] = rn;
            const float TWO_PI = 6.2831853071795864769f;
#pragma unroll
            for (int i = 0; i < 8; i++) {
                float fr = exp2f((float)i * 0.29024101186092026f);  // 5^(i/8)
                float ang = TWO_PI * rn * fr;
                f[12 + d * 16 + i] = sinf(ang);
                f[12 + d * 16 + 8 + i] = cosf(ang);
            }
        }
        for (int c = 0; c < 64; c += 2) {
            uint32_t hw, lw; split2(f[c], f[c + 1], hw, lw);
            ah[(base + 96 + c) >> 1] = hw;
            al[(base + 96 + c) >> 1] = lw;
        }
    }

    // ldmatrix base addresses (bytes)
    const uint32_t aH = smb + SM_AH + ((mw * 16 + (lane & 15)) * ASTR + (lane >> 4) * 8) * 2;
    const uint32_t aL = aH + (SM_AL - SM_AH);
    const uint32_t wHb = smb + SM_WH + ((lane & 15) * WSTR) * 2;
    const uint32_t wLb = wHb + (SM_WL - SM_WH);

    // ---- 7 rounds: L0, L1, L2, L0', L1', L2', post ----
    const float* Wt[7] = {w00, w01, w02, w10, w11, w12, pw};
    const float* Bt[7] = {b00, b01, b02, b10, b11, b12, pb};
    const int Kreal[7] = {156, 96, 96, 156, 96, 96, 96};
    const int Kpad[7]  = {160, 96, 96, 160, 96, 96, 96};
    const int ldw[7]   = {96, 96, 96, 96, 96, 96, OUTC};
    const int nval[7]  = {96, 96, 96, 96, 96, 96, OUTC};
    const int npr[7]   = {48, 48, 48, 48, 48, 48, 24};   // n-pairs per k row

    const int r0 = mw * 16 + (lane >> 2);
    const int r1 = r0 + 8;
    const int cb = (lane & 3) * 2;

    float2 pf[15];
    ldg_w(Wt[0], ldw[0], nval[0], Kreal[0], Kpad[0], npr[0], pf, tid);

#pragma unroll 1
    for (int r = 0; r < 7; r++) {
        __syncthreads();   // prev round done: weights free, act writes visible
        sts_w(Kpad[r], npr[r], pf, smc, tid);
        float* bias = pbF + (r & 1) * 96;
        if (tid < 96) bias[tid] = (tid < nval[r]) ? Bt[r][tid] : 0.0f;
        __syncthreads();   // weights visible
        if (r < 6)
            ldg_w(Wt[r + 1], ldw[r + 1], nval[r + 1], Kreal[r + 1], Kpad[r + 1],
                  npr[r + 1], pf, tid);   // overlaps with MMA below

        if (r < 6) {
            float acc[6][4];
#pragma unroll
            for (int t = 0; t < 6; t++)
                acc[t][0] = acc[t][1] = acc[t][2] = acc[t][3] = 0.0f;
            do_round<6>(acc, Kpad[r] >> 4, aH, aL, wHb + nw * 96, wLb + nw * 96);

            // Both warps of this row-pair read ALL columns of rows r0/r1 above;
            // neither may overwrite A until the other's ldmatrix reads are done.
            pair_bar(mw);

            bool skip = (r % 3 == 2);
            uint32_t* ah = (uint32_t*)(smc + SM_AH);
            uint32_t* al = (uint32_t*)(smc + SM_AL);
#pragma unroll
            for (int t = 0; t < 6; t++) {
                int c = (nw * 6 + t) * 8 + cb;
                float b0 = bias[c], b1 = bias[c + 1];
                float a0 = silu(acc[t][0] + b0), a1 = silu(acc[t][1] + b1);
                float a2 = silu(acc[t][2] + b0), a3 = silu(acc[t][3] + b1);
                if (skip) {
                    a0 += xS[r0 * XSTRF + c];
                    a1 += xS[r0 * XSTRF + c + 1];
                    a2 += xS[r1 * XSTRF + c];
                    a3 += xS[r1 * XSTRF + c + 1];
                    xS[r0 * XSTRF + c] = a0;
                    xS[r0 * XSTRF + c + 1] = a1;
                    xS[r1 * XSTRF + c] = a2;
                    xS[r1 * XSTRF + c + 1] = a3;
                }
                uint32_t hw, lw;
                split2(a0, a1, hw, lw);
                ah[(r0 * ASTR + c) >> 1] = hw;
                al[(r0 * ASTR + c) >> 1] = lw;
                split2(a2, a3, hw, lw);
                ah[(r1 * ASTR + c) >> 1] = hw;
                al[(r1 * ASTR + c) >> 1] = lw;
            }
        } else {
            float acc[3][4];
#pragma unroll
            for (int t = 0; t < 3; t++)
                acc[t][0] = acc[t][1] = acc[t][2] = acc[t][3] = 0.0f;
            do_round<3>(acc, 6, aH, aL, wHb + nw * 48, wLb + nw * 48);

            float w8a = w8S[r0], w8b = w8S[r1];
            int ptA = mw * 2, ptB = mw * 2 + 1;
#pragma unroll
            for (int t = 0; t < 3; t++) {
                int c = (nw * 3 + t) * 8 + cb;
                float b0 = bias[c], b1 = bias[c + 1];
                float v0 = (acc[t][0] + b0) * w8a;
                float v1 = (acc[t][1] + b1) * w8a;
                float v2 = (acc[t][2] + b0) * w8b;
                float v3 = (acc[t][3] + b1) * w8b;
#pragma unroll
                for (int m = 4; m <= 16; m <<= 1) {
                    v0 += __shfl_xor_sync(0xffffffffu, v0, m);
                    v1 += __shfl_xor_sync(0xffffffffu, v1, m);
                    v2 += __shfl_xor_sync(0xffffffffu, v2, m);
                    v3 += __shfl_xor_sync(0xffffffffu, v3, m);
                }
                if ((lane >> 2) == 0) {
                    if (c < OUTC) {
                        out[c * QTOT + pbase + ptA] = v0;
                        out[c * QTOT + pbase + ptB] = v2;
                    }
                    if (c + 1 < OUTC) {
                        out[(c + 1) * QTOT + pbase + ptA] = v1;
                        out[(c + 1) * QTOT + pbase + ptB] = v3;
                    }
                }
            }
        }
    }

    // Self-reset of the global-min scratch for the next graph replay:
    // the last block to finish restores the sentinel and the counter.
    if (tid == 0) {
        __threadfence();
        unsigned old = atomicAdd(&g_done, 1u);
        if (old == (unsigned)(gridDim.x - 1)) {
            g_min_enc[0] = 0xFFFFFFFFu;
            g_min_enc[1] = 0xFFFFFFFFu;
            g_min_enc[2] = 0xFFFFFFFFu;
            g_done = 0;
        }
    }
}

extern "C" void kernel_launch(void* const* d_in, const int* in_sizes, int n_in,
                              void* d_out, int out_size) {
    const float* ctxv = (const float*)d_in[0];
    const float* ext  = (const float*)d_in[1];
    const float* qvs  = (const float*)d_in[2];
    const float* qc   = (const float*)d_in[3];
    const float* w00 = (const float*)d_in[4];
    const float* b00 = (const float*)d_in[5];
    const float* w01 = (const float*)d_in[6];
    const float* b01 = (const float*)d_in[7];
    const float* w02 = (const float*)d_in[8];
    const float* b02 = (const float*)d_in[9];
    const float* w10 = (const float*)d_in[10];
    const float* b10 = (const float*)d_in[11];
    const float* w11 = (const float*)d_in[12];
    const float* b11 = (const float*)d_in[13];
    const float* w12 = (const float*)d_in[14];
    const float* b12 = (const float*)d_in[15];
    const float* pw  = (const float*)d_in[16];
    const float* pb  = (const float*)d_in[17];
    float* out = (float*)d_out;

    cudaFuncSetAttribute(main_kernel, cudaFuncAttributeMaxDynamicSharedMemorySize, SMEM_TOTAL);

    min_kernel<<<QTOT / 256, 256>>>(ext, qc);
    main_kernel<<<QTOT / PTSB, THREADS, SMEM_TOTAL>>>(
        ctxv, ext, qvs, qc,
        w00, b00, w01, b01, w02, b02,
        w10, b10, w11, b11, w12, b12,
        pw, pb, out);
}

// round 16
// speedup vs baseline: 2.5252x; 1.4756x over previous
#include <cuda_runtime.h>
#include <cuda_bf16.h>
#include <stdint.h>
#include <math.h>

#define QTOT 110592
#define OUTC 45
#define PTSB 16
#define TROWS 128
#define THREADS 512

#define ASTR 168            // act plane stride (bf16 elems), 336B
#define WSTR 104            // weight plane stride (bf16 elems), 208B
#define XSTRF 100           // fp32 skip-state stride
#define WPLANE 16640        // 160*104 bf16 per round per plane

// smem byte offsets
#define SM_AH 0                          // bf16 [128][168] hi  43008
#define SM_AL 43008                      // bf16 [128][168] lo  43008
#define SM_WH 86016                      // bf16 [160][104] hi  33280
#define SM_WL 119296                     // bf16 [160][104] lo  33280
#define SM_XS 152576                     // fp32 [128][100]     51200
#define SM_RB 203776                     // int[128]
#define SM_W8 204288                     // float[128]
#define SM_PTQ 204800                    // float[48]
#define SM_PTR 204992                    // float[48]
#define SM_PTT 205184                    // float[48]
#define SM_NEAR 205376                   // int[48]
#define SM_MISC 205568                   // qv[3]@0 vox[3]@12 min[3]@24
#define SMEM_TOTAL 205632

__device__ unsigned int g_min_enc[3] = {0xFFFFFFFFu, 0xFFFFFFFFu, 0xFFFFFFFFu};
__device__ unsigned int g_done = 0;
// Pre-converted weight planes: [7 rounds][160][104] bf16, smem-identical layout.
__device__ __align__(16) __nv_bfloat16 g_whi[7 * WPLANE];
__device__ __align__(16) __nv_bfloat16 g_wlo[7 * WPLANE];

__device__ __forceinline__ unsigned fenc(float f) {
    unsigned u = __float_as_uint(f);
    return (u & 0x80000000u) ? ~u : (u | 0x80000000u);
}
__device__ __forceinline__ float fdec(unsigned e) {
    return __uint_as_float((e & 0x80000000u) ? (e ^ 0x80000000u) : ~e);
}
__device__ __forceinline__ float silu(float x) {
    return x * (1.0f / (1.0f + __expf(-x)));
}
__device__ __forceinline__ void split2(float a, float b, uint32_t& hw, uint32_t& lw) {
    __nv_bfloat16 ha = __float2bfloat16(a), hb = __float2bfloat16(b);
    __nv_bfloat16 la = __float2bfloat16(a - __bfloat162float(ha));
    __nv_bfloat16 lb = __float2bfloat16(b - __bfloat162float(hb));
    hw = (uint32_t)__bfloat16_as_ushort(ha) | ((uint32_t)__bfloat16_as_ushort(hb) << 16);
    lw = (uint32_t)__bfloat16_as_ushort(la) | ((uint32_t)__bfloat16_as_ushort(lb) << 16);
}

// ---- baseline-PTX tensor ops (sm_80-era; no 'a' target required) ----
__device__ __forceinline__ void ldsm4(uint32_t* r, uint32_t a) {
    asm volatile("ldmatrix.sync.aligned.m8n8.x4.shared.b16 {%0,%1,%2,%3}, [%4];"
                 : "=r"(r[0]), "=r"(r[1]), "=r"(r[2]), "=r"(r[3]) : "r"(a));
}
__device__ __forceinline__ void ldsm4t(uint32_t* r, uint32_t a) {
    asm volatile("ldmatrix.sync.aligned.m8n8.x4.trans.shared.b16 {%0,%1,%2,%3}, [%4];"
                 : "=r"(r[0]), "=r"(r[1]), "=r"(r[2]), "=r"(r[3]) : "r"(a));
}
__device__ __forceinline__ void ldsm2t(uint32_t* r, uint32_t a) {
    asm volatile("ldmatrix.sync.aligned.m8n8.x2.trans.shared.b16 {%0,%1}, [%2];"
                 : "=r"(r[0]), "=r"(r[1]) : "r"(a));
}
__device__ __forceinline__ void mmabf(float* d, const uint32_t* a, const uint32_t* b) {
    asm volatile(
        "mma.sync.aligned.m16n8k16.row.col.f32.bf16.bf16.f32 "
        "{%0,%1,%2,%3}, {%4,%5,%6,%7}, {%8,%9}, {%0,%1,%2,%3};"
        : "+f"(d[0]), "+f"(d[1]), "+f"(d[2]), "+f"(d[3])
        : "r"(a[0]), "r"(a[1]), "r"(a[2]), "r"(a[3]), "r"(b[0]), "r"(b[1]));
}
__device__ __forceinline__ void cp16(uint32_t dst, const void* src) {
    asm volatile("cp.async.cg.shared.global [%0], [%1], 16;"
                 :: "r"(dst), "l"(src) : "memory");
}
#define CP_COMMIT() asm volatile("cp.async.commit_group;" ::: "memory")
#define CP_WAIT0()  asm volatile("cp.async.wait_group 0;" ::: "memory")

__global__ void min_kernel(const float* __restrict__ ext, const float* __restrict__ qc) {
    int p = blockIdx.x * blockDim.x + threadIdx.x;
    float raw[3] = {1e30f, 1e30f, 1e30f};
    if (p < QTOT) {
        int ni[3]; float q[3];
#pragma unroll
        for (int d = 0; d < 3; d++) {
            float o = ext[d * 32768];
            float v = fabsf(ext[d * 32768 + 1057] - o);
            q[d] = qc[d * QTOT + p];
            int n = __float2int_rn((q[d] - o) / v);
            ni[d] = min(max(n, 0), 30);
        }
#pragma unroll
        for (int d = 0; d < 3; d++)
            raw[d] = ext[d * 32768 + ni[0] * 1024 + ni[1] * 32 + ni[2]] - q[d];
    }
#pragma unroll
    for (int off = 16; off; off >>= 1)
#pragma unroll
        for (int d = 0; d < 3; d++)
            raw[d] = fminf(raw[d], __shfl_down_sync(0xffffffffu, raw[d], off));
    if ((threadIdx.x & 31) == 0)
#pragma unroll
        for (int d = 0; d < 3; d++)
            atomicMin(&g_min_enc[d], fenc(raw[d]));
}

// One-time weight conversion: fp32 [K][ldw] -> bf16 hi/lo planes, smem layout.
__global__ void prep_w(const float* __restrict__ w00, const float* __restrict__ w01,
                       const float* __restrict__ w02, const float* __restrict__ w10,
                       const float* __restrict__ w11, const float* __restrict__ w12,
                       const float* __restrict__ pw) {
    const float* Wt[7] = {w00, w01, w02, w10, w11, w12, pw};
    const int Kreal[7] = {156, 96, 96, 156, 96, 96, 96};
    const int ldw[7]   = {96, 96, 96, 96, 96, 96, OUTC};
    const int nval[7]  = {96, 96, 96, 96, 96, 96, OUTC};
    int idx = blockIdx.x * blockDim.x + threadIdx.x;
    if (idx >= 7 * WPLANE) return;
    int r = idx / WPLANE, rem = idx - r * WPLANE;
    int k = rem / WSTR, n = rem - k * WSTR;
    float v = (k < Kreal[r] && n < nval[r]) ? Wt[r][k * ldw[r] + n] : 0.0f;
    __nv_bfloat16 hi = __float2bfloat16(v);
    __nv_bfloat16 lo = __float2bfloat16(v - __bfloat162float(hi));
    g_whi[idx] = hi;
    g_wlo[idx] = lo;
}

// Async stage of round r's weight planes into smem (16B chunks). Commits group.
__device__ __forceinline__ void cpw(int r, int kpad, uint32_t smb, int tid) {
    const char* srcH = (const char*)(g_whi + r * WPLANE);
    const char* srcL = (const char*)(g_wlo + r * WPLANE);
    uint32_t dstH = smb + SM_WH, dstL = smb + SM_WL;
    int chunks = kpad * 13;          // 208B per k-row = 13 x 16B
    for (int t = tid; t < chunks; t += THREADS) {
        int off = t * 16;
        cp16(dstH + off, srcH + off);
        cp16(dstL + off, srcL + off);
    }
    CP_COMMIT();
}

// One GEMM round per warp: acc += A[16 rows x 16*ksteps] * W[NT n8-tiles].
// B loaded with x4.trans (two n8 tiles per ldmatrix).
template <int NT>
__device__ __forceinline__ void do_round(float (&acc)[NT][4], int ksteps,
                                         uint32_t aH, uint32_t aL,
                                         uint32_t wH, uint32_t wL) {
#pragma unroll 1
    for (int k = 0; k < ksteps; k++) {
        uint32_t ah[4], al[4];
        ldsm4(ah, aH + k * 32);
        ldsm4(al, aL + k * 32);
        uint32_t wkH = wH + k * 16 * (WSTR * 2);
        uint32_t wkL = wL + k * 16 * (WSTR * 2);
#pragma unroll
        for (int tp = 0; tp < NT / 2; tp++) {
            uint32_t bh[4], bl[4];
            ldsm4t(bh, wkH + tp * 32);
            ldsm4t(bl, wkL + tp * 32);
            mmabf(acc[2 * tp], ah, bh);
            mmabf(acc[2 * tp], ah, bl);
            mmabf(acc[2 * tp], al, bh);
            mmabf(acc[2 * tp + 1], ah, bh + 2);
            mmabf(acc[2 * tp + 1], ah, bl + 2);
            mmabf(acc[2 * tp + 1], al, bh + 2);
        }
        if (NT & 1) {
            uint32_t bh[2], bl[2];
            ldsm2t(bh, wkH + (NT - 1) * 16);
            ldsm2t(bl, wkL + (NT - 1) * 16);
            mmabf(acc[NT - 1], ah, bh);
            mmabf(acc[NT - 1], ah, bl);
            mmabf(acc[NT - 1], al, bh);
        }
    }
}

__global__ __launch_bounds__(THREADS, 1) void main_kernel(
    const float* __restrict__ ctxv, const float* __restrict__ ext,
    const float* __restrict__ qvs, const float* __restrict__ qc,
    const float* __restrict__ b00, const float* __restrict__ b01,
    const float* __restrict__ b02, const float* __restrict__ b10,
    const float* __restrict__ b11, const float* __restrict__ b12,
    const float* __restrict__ pb,
    float* __restrict__ out) {
    extern __shared__ char smc[];
    float* xS    = (float*)(smc + SM_XS);
    int* rowBase = (int*)(smc + SM_RB);
    float* w8S   = (float*)(smc + SM_W8);
    float* ptQ   = (float*)(smc + SM_PTQ);
    float* ptR   = (float*)(smc + SM_PTR);
    float* ptT   = (float*)(smc + SM_PTT);
    int* nearS   = (int*)(smc + SM_NEAR);
    float* qvS   = (float*)(smc + SM_MISC);
    float* voxS  = qvS + 3;
    float* minS  = voxS + 3;

    const int tid = threadIdx.x;
    const int lane = tid & 31;
    const int warp = tid >> 5;
    const int mw = warp >> 1;      // 0..7: 16-row slice
    const int nw = warp & 1;       // 0..1: N half
    const int pbase = blockIdx.x * PTSB;
    const uint32_t smb = (uint32_t)__cvta_generic_to_shared(smc);

    // Kick off round-0 weight staging immediately (overlaps feature setup).
    cpw(0, 160, smb, tid);

    // ---- feature setup ----
    if (tid < 3) {
        float o = ext[tid * 32768];
        qvS[tid] = qvs[tid];
        voxS[tid] = fabsf(ext[tid * 32768 + 1057] - o);
        minS[tid] = fdec(g_min_enc[tid]);
    }
    if (tid < 48) {
        int pt = tid / 3, d = tid - pt * 3;
        float o = ext[d * 32768];
        float v = fabsf(ext[d * 32768 + 1057] - o);
        float q = qc[d * QTOT + pbase + pt];
        int n = __float2int_rn((q - o) / v);
        nearS[tid] = min(max(n, 0), 30);
        ptQ[tid] = q;
    }
    __syncthreads();
    if (tid < 48) {
        int pt = tid / 3, d = tid - pt * 3;
        float cc = ext[d * 32768 + nearS[pt * 3] * 1024 + nearS[pt * 3 + 1] * 32 + nearS[pt * 3 + 2]];
        float raw = cc - ptQ[tid];
        ptR[tid] = raw;
        float v = voxS[d];
        float clampc = fmaf(v, -0.5f, 1e-7f);
        float rel0 = fmaxf(raw, clampc);
        float g = fminf(fmaxf((rel0 - 0.5f) * 2.0f, -1.0f + 1e-7f), 1.0f - 1e-7f);
        ptT[tid] = (g + 1.0f) * 0.5f;
    }
    if (tid < TROWS) {
        int pt = tid >> 3, cn = tid & 7;
        int ix = nearS[pt * 3 + 0] + ((cn >> 2) & 1);
        int iy = nearS[pt * 3 + 1] + ((cn >> 1) & 1);
        int iz = nearS[pt * 3 + 2] + (cn & 1);
        rowBase[tid] = ix * 1024 + iy * 32 + iz;
    }
    __syncthreads();
    if (tid < TROWS) {
        int pt = tid >> 3, cn = tid & 7;
        float wi = ((cn >> 2) & 1) ? ptT[pt * 3 + 2] : 1.0f - ptT[pt * 3 + 2];
        float wj = ((cn >> 1) & 1) ? ptT[pt * 3 + 1] : 1.0f - ptT[pt * 3 + 1];
        float wk = (cn & 1) ? ptT[pt * 3 + 0] : 1.0f - ptT[pt * 3 + 0];
        w8S[tid] = wi * wj * wk;
    }
    // context gather -> xS (fp32 skip state)
    for (int idx = tid; idx < TROWS * 96; idx += THREADS) {
        int row = idx & 127, c = idx >> 7;
        xS[row * XSTRF + c] = ctxv[c * 32768 + rowBase[row]];
    }
    __syncthreads();

    // ---- initial act fill: cols 0..95 = x, 96..155 = coord feats, 156..159 = 0
    if (tid < TROWS) {
        int row = tid;
        uint32_t* ah = (uint32_t*)(smc + SM_AH);
        uint32_t* al = (uint32_t*)(smc + SM_AL);
        float* xrow = xS + row * XSTRF;
        int base = row * ASTR;
        for (int c = 0; c < 96; c += 2) {
            uint32_t hw, lw; split2(xrow[c], xrow[c + 1], hw, lw);
            ah[(base + c) >> 1] = hw;
            al[(base + c) >> 1] = lw;
        }
        int pt = row >> 3, cn = row & 7;
        float f[64];
        f[60] = f[61] = f[62] = f[63] = 0.f;
        int rb = rowBase[row];
#pragma unroll
        for (int d = 0; d < 3; d++) {
            int off = (d == 0) ? ((cn >> 2) & 1) : (d == 1) ? ((cn >> 1) & 1) : (cn & 1);
            float v = voxS[d];
            float clampc = fmaf(v, -0.5f, 1e-7f);
            float raw = ptR[pt * 3 + d] + (float)off * v;
            float rel = fmaxf(raw, clampc);
            float rmin = fmaxf(minS[d] + (float)off * v, clampc);
            float rn = (rel - rmin) / (1.5f * v);
            f[d] = qvS[d];
            f[3 + d] = ext[d * 32768 + rb];
            f[6 + d] = ptQ[pt * 3 + d];
            f[9 + d] = rn;
            const float TWO_PI = 6.2831853071795864769f;
#pragma unroll
            for (int i = 0; i < 8; i++) {
                float fr = exp2f((float)i * 0.29024101186092026f);  // 5^(i/8)
                float ang = TWO_PI * rn * fr;
                f[12 + d * 16 + i] = __sinf(ang);
                f[12 + d * 16 + 8 + i] = __cosf(ang);
            }
        }
        for (int c = 0; c < 64; c += 2) {
            uint32_t hw, lw; split2(f[c], f[c + 1], hw, lw);
            ah[(base + 96 + c) >> 1] = hw;
            al[(base + 96 + c) >> 1] = lw;
        }
    }

    // ldmatrix base addresses (bytes)
    const uint32_t aH = smb + SM_AH + ((mw * 16 + (lane & 15)) * ASTR + (lane >> 4) * 8) * 2;
    const uint32_t aL = aH + (SM_AL - SM_AH);
    // B base includes the x4 second-half n-offset term; harmless for x2 (lanes 0-15).
    const uint32_t wHb = smb + SM_WH + (((lane & 15)) * WSTR + (lane >> 4) * 8) * 2;
    const uint32_t wLb = wHb + (SM_WL - SM_WH);

    // ---- 7 rounds: L0, L1, L2, L0', L1', L2', post ----
    const float* Bt[7] = {b00, b01, b02, b10, b11, b12, pb};
    const int Kpad[7]  = {160, 96, 96, 160, 96, 96, 96};

    const int r0 = mw * 16 + (lane >> 2);
    const int r1 = r0 + 8;
    const int cb = (lane & 3) * 2;
    uint32_t* ahp = (uint32_t*)(smc + SM_AH);
    uint32_t* alp = (uint32_t*)(smc + SM_AL);

#pragma unroll 1
    for (int r = 0; r < 7; r++) {
        CP_WAIT0();
        __syncthreads();   // W[r] + prev-round A writes visible everywhere

        if (r < 6) {
            float acc[6][4];
#pragma unroll
            for (int t = 0; t < 6; t++)
                acc[t][0] = acc[t][1] = acc[t][2] = acc[t][3] = 0.0f;
            do_round<6>(acc, Kpad[r] >> 4, aH, aL, wHb + nw * 96, wLb + nw * 96);

            __syncthreads();   // all W[r] reads + A reads done
            cpw(r + 1, Kpad[r + 1], smb, tid);   // copy flies during epilogue

            bool skip = (r % 3 == 2);
            const float* bias = Bt[r];
#pragma unroll
            for (int t = 0; t < 6; t++) {
                int c = (nw * 6 + t) * 8 + cb;
                float b0 = __ldg(bias + c), b1 = __ldg(bias + c + 1);
                float a0 = silu(acc[t][0] + b0), a1 = silu(acc[t][1] + b1);
                float a2 = silu(acc[t][2] + b0), a3 = silu(acc[t][3] + b1);
                if (skip) {
                    a0 += xS[r0 * XSTRF + c];
                    a1 += xS[r0 * XSTRF + c + 1];
                    a2 += xS[r1 * XSTRF + c];
                    a3 += xS[r1 * XSTRF + c + 1];
                    xS[r0 * XSTRF + c] = a0;
                    xS[r0 * XSTRF + c + 1] = a1;
                    xS[r1 * XSTRF + c] = a2;
                    xS[r1 * XSTRF + c + 1] = a3;
                }
                uint32_t hw, lw;
                split2(a0, a1, hw, lw);
                ahp[(r0 * ASTR + c) >> 1] = hw;
                alp[(r0 * ASTR + c) >> 1] = lw;
                split2(a2, a3, hw, lw);
                ahp[(r1 * ASTR + c) >> 1] = hw;
                alp[(r1 * ASTR + c) >> 1] = lw;
            }
        } else {
            float acc[3][4];
#pragma unroll
            for (int t = 0; t < 3; t++)
                acc[t][0] = acc[t][1] = acc[t][2] = acc[t][3] = 0.0f;
            do_round<3>(acc, 6, aH, aL, wHb + nw * 48, wLb + nw * 48);

            float w8a = w8S[r0], w8b = w8S[r1];
            int ptA = mw * 2, ptB = mw * 2 + 1;
#pragma unroll
            for (int t = 0; t < 3; t++) {
                int c = (nw * 3 + t) * 8 + cb;
                float b0 = (c < OUTC) ? __ldg(pb + c) : 0.0f;
                float b1 = (c + 1 < OUTC) ? __ldg(pb + c + 1) : 0.0f;
                float v0 = (acc[t][0] + b0) * w8a;
                float v1 = (acc[t][1] + b1) * w8a;
                float v2 = (acc[t][2] + b0) * w8b;
                float v3 = (acc[t][3] + b1) * w8b;
#pragma unroll
                for (int m = 4; m <= 16; m <<= 1) {
                    v0 += __shfl_xor_sync(0xffffffffu, v0, m);
                    v1 += __shfl_xor_sync(0xffffffffu, v1, m);
                    v2 += __shfl_xor_sync(0xffffffffu, v2, m);
                    v3 += __shfl_xor_sync(0xffffffffu, v3, m);
                }
                if ((lane >> 2) == 0) {
                    if (c < OUTC) {
                        out[c * QTOT + pbase + ptA] = v0;
                        out[c * QTOT + pbase + ptB] = v2;
                    }
                    if (c + 1 < OUTC) {
                        out[(c + 1) * QTOT + pbase + ptA] = v1;
                        out[(c + 1) * QTOT + pbase + ptB] = v3;
                    }
                }
            }
        }
    }

    // Self-reset of the global-min scratch for the next graph replay.
    if (tid == 0) {
        __threadfence();
        unsigned old = atomicAdd(&g_done, 1u);
        if (old == (unsigned)(gridDim.x - 1)) {
            g_min_enc[0] = 0xFFFFFFFFu;
            g_min_enc[1] = 0xFFFFFFFFu;
            g_min_enc[2] = 0xFFFFFFFFu;
            g_done = 0;
        }
    }
}

extern "C" void kernel_launch(void* const* d_in, const int* in_sizes, int n_in,
                              void* d_out, int out_size) {
    const float* ctxv = (const float*)d_in[0];
    const float* ext  = (const float*)d_in[1];
    const float* qvs  = (const float*)d_in[2];
    const float* qc   = (const float*)d_in[3];
    const float* w00 = (const float*)d_in[4];
    const float* b00 = (const float*)d_in[5];
    const float* w01 = (const float*)d_in[6];
    const float* b01 = (const float*)d_in[7];
    const float* w02 = (const float*)d_in[8];
    const float* b02 = (const float*)d_in[9];
    const float* w10 = (const float*)d_in[10];
    const float* b10 = (const float*)d_in[11];
    const float* w11 = (const float*)d_in[12];
    const float* b11 = (const float*)d_in[13];
    const float* w12 = (const float*)d_in[14];
    const float* b12 = (const float*)d_in[15];
    const float* pw  = (const float*)d_in[16];
    const float* pb  = (const float*)d_in[17];
    float* out = (float*)d_out;

    cudaFuncSetAttribute(main_kernel, cudaFuncAttributeMaxDynamicSharedMemorySize, SMEM_TOTAL);

    min_kernel<<<QTOT / 256, 256>>>(ext, qc);
    prep_w<<<(7 * WPLANE + 255) / 256, 256>>>(w00, w01, w02, w10, w11, w12, pw);
    main_kernel<<<QTOT / PTSB, THREADS, SMEM_TOTAL>>>(
        ctxv, ext, qvs, qc,
        b00, b01, b02, b10, b11, b12, pb,
        out);
}

// round 17
// speedup vs baseline: 3.0335x; 1.2013x over previous
#include <cuda_runtime.h>
#include <cuda_bf16.h>
#include <stdint.h>
#include <math.h>

#define QTOT 110592
#define OUTC 45
#define PTSB 8
#define TROWS 64
#define THREADS 256

#define ASTR 168            // act plane stride (bf16 elems), 336B
#define WSTR 104            // weight plane stride (bf16 elems), 208B
#define WPLANE 16640        // 160*104 bf16 per round per plane

// smem byte offsets (total 110512 -> 2 CTAs/SM)
#define SM_AH 0                          // bf16 [64][168] hi   21504
#define SM_AL 21504                      // bf16 [64][168] lo   21504
#define SM_WH 43008                      // bf16 [160][104] hi  33280
#define SM_WL 76288                      // bf16 [160][104] lo  33280
#define SM_RB 109568                     // int[64]
#define SM_W8 109824                     // float[64]
#define SM_PTQ 110080                    // float[24]
#define SM_PTR 110176                    // float[24]
#define SM_PTT 110272                    // float[24]
#define SM_NEAR 110368                   // int[24]
#define SM_MISC 110464                   // qv[3]@0 vox[3]@12 min[3]@24
#define SMEM_TOTAL 110512

__device__ unsigned int g_min_enc[3] = {0xFFFFFFFFu, 0xFFFFFFFFu, 0xFFFFFFFFu};
__device__ unsigned int g_done = 0;
// Pre-converted weight planes: [7 rounds][160][104] bf16, smem-identical layout.
__device__ __align__(16) __nv_bfloat16 g_whi[7 * WPLANE];
__device__ __align__(16) __nv_bfloat16 g_wlo[7 * WPLANE];

__device__ __forceinline__ unsigned fenc(float f) {
    unsigned u = __float_as_uint(f);
    return (u & 0x80000000u) ? ~u : (u | 0x80000000u);
}
__device__ __forceinline__ float fdec(unsigned e) {
    return __uint_as_float((e & 0x80000000u) ? (e ^ 0x80000000u) : ~e);
}
__device__ __forceinline__ float silu(float x) {
    return x * (1.0f / (1.0f + __expf(-x)));
}
__device__ __forceinline__ void split2(float a, float b, uint32_t& hw, uint32_t& lw) {
    __nv_bfloat16 ha = __float2bfloat16(a), hb = __float2bfloat16(b);
    __nv_bfloat16 la = __float2bfloat16(a - __bfloat162float(ha));
    __nv_bfloat16 lb = __float2bfloat16(b - __bfloat162float(hb));
    hw = (uint32_t)__bfloat16_as_ushort(ha) | ((uint32_t)__bfloat16_as_ushort(hb) << 16);
    lw = (uint32_t)__bfloat16_as_ushort(la) | ((uint32_t)__bfloat16_as_ushort(lb) << 16);
}

// ---- baseline-PTX tensor ops ----
__device__ __forceinline__ void ldsm4(uint32_t* r, uint32_t a) {
    asm volatile("ldmatrix.sync.aligned.m8n8.x4.shared.b16 {%0,%1,%2,%3}, [%4];"
                 : "=r"(r[0]), "=r"(r[1]), "=r"(r[2]), "=r"(r[3]) : "r"(a));
}
__device__ __forceinline__ void ldsm4t(uint32_t* r, uint32_t a) {
    asm volatile("ldmatrix.sync.aligned.m8n8.x4.trans.shared.b16 {%0,%1,%2,%3}, [%4];"
                 : "=r"(r[0]), "=r"(r[1]), "=r"(r[2]), "=r"(r[3]) : "r"(a));
}
__device__ __forceinline__ void ldsm2t(uint32_t* r, uint32_t a) {
    asm volatile("ldmatrix.sync.aligned.m8n8.x2.trans.shared.b16 {%0,%1}, [%2];"
                 : "=r"(r[0]), "=r"(r[1]) : "r"(a));
}
__device__ __forceinline__ void mmabf(float* d, const uint32_t* a, const uint32_t* b) {
    asm volatile(
        "mma.sync.aligned.m16n8k16.row.col.f32.bf16.bf16.f32 "
        "{%0,%1,%2,%3}, {%4,%5,%6,%7}, {%8,%9}, {%0,%1,%2,%3};"
        : "+f"(d[0]), "+f"(d[1]), "+f"(d[2]), "+f"(d[3])
        : "r"(a[0]), "r"(a[1]), "r"(a[2]), "r"(a[3]), "r"(b[0]), "r"(b[1]));
}
__device__ __forceinline__ void cp16(uint32_t dst, const void* src) {
    asm volatile("cp.async.cg.shared.global [%0], [%1], 16;"
                 :: "r"(dst), "l"(src) : "memory");
}
#define CP_COMMIT() asm volatile("cp.async.commit_group;" ::: "memory")
#define CP_WAIT0()  asm volatile("cp.async.wait_group 0;" ::: "memory")

__global__ void min_kernel(const float* __restrict__ ext, const float* __restrict__ qc) {
    int p = blockIdx.x * blockDim.x + threadIdx.x;
    float raw[3] = {1e30f, 1e30f, 1e30f};
    if (p < QTOT) {
        int ni[3]; float q[3];
#pragma unroll
        for (int d = 0; d < 3; d++) {
            float o = ext[d * 32768];
            float v = fabsf(ext[d * 32768 + 1057] - o);
            q[d] = qc[d * QTOT + p];
            int n = __float2int_rn((q[d] - o) / v);
            ni[d] = min(max(n, 0), 30);
        }
#pragma unroll
        for (int d = 0; d < 3; d++)
            raw[d] = ext[d * 32768 + ni[0] * 1024 + ni[1] * 32 + ni[2]] - q[d];
    }
#pragma unroll
    for (int off = 16; off; off >>= 1)
#pragma unroll
        for (int d = 0; d < 3; d++)
            raw[d] = fminf(raw[d], __shfl_down_sync(0xffffffffu, raw[d], off));
    if ((threadIdx.x & 31) == 0)
#pragma unroll
        for (int d = 0; d < 3; d++)
            atomicMin(&g_min_enc[d], fenc(raw[d]));
}

// One-time weight conversion: fp32 [K][ldw] -> bf16 hi/lo planes, smem layout.
__global__ void prep_w(const float* __restrict__ w00, const float* __restrict__ w01,
                       const float* __restrict__ w02, const float* __restrict__ w10,
                       const float* __restrict__ w11, const float* __restrict__ w12,
                       const float* __restrict__ pw) {
    const float* Wt[7] = {w00, w01, w02, w10, w11, w12, pw};
    const int Kreal[7] = {156, 96, 96, 156, 96, 96, 96};
    const int ldw[7]   = {96, 96, 96, 96, 96, 96, OUTC};
    const int nval[7]  = {96, 96, 96, 96, 96, 96, OUTC};
    int idx = blockIdx.x * blockDim.x + threadIdx.x;
    if (idx >= 7 * WPLANE) return;
    int r = idx / WPLANE, rem = idx - r * WPLANE;
    int k = rem / WSTR, n = rem - k * WSTR;
    float v = (k < Kreal[r] && n < nval[r]) ? Wt[r][k * ldw[r] + n] : 0.0f;
    __nv_bfloat16 hi = __float2bfloat16(v);
    __nv_bfloat16 lo = __float2bfloat16(v - __bfloat162float(hi));
    g_whi[idx] = hi;
    g_wlo[idx] = lo;
}

// Async stage of round r's weight planes into smem (16B chunks). Commits group.
__device__ __forceinline__ void cpw(int r, int kpad, uint32_t smb, int tid) {
    const char* srcH = (const char*)(g_whi + r * WPLANE);
    const char* srcL = (const char*)(g_wlo + r * WPLANE);
    uint32_t dstH = smb + SM_WH, dstL = smb + SM_WL;
    int chunks = kpad * 13;          // 208B per k-row = 13 x 16B
    for (int t = tid; t < chunks; t += THREADS) {
        int off = t * 16;
        cp16(dstH + off, srcH + off);
        cp16(dstL + off, srcL + off);
    }
    CP_COMMIT();
}

// One GEMM round per warp: acc += A[16 rows x 16*ksteps] * W[NT n8-tiles].
template <int NT>
__device__ __forceinline__ void do_round(float (&acc)[NT][4], int ksteps,
                                         uint32_t aH, uint32_t aL,
                                         uint32_t wH, uint32_t wL) {
#pragma unroll 1
    for (int k = 0; k < ksteps; k++) {
        uint32_t ah[4], al[4];
        ldsm4(ah, aH + k * 32);
        ldsm4(al, aL + k * 32);
        uint32_t wkH = wH + k * 16 * (WSTR * 2);
        uint32_t wkL = wL + k * 16 * (WSTR * 2);
#pragma unroll
        for (int tp = 0; tp < NT / 2; tp++) {
            uint32_t bh[4], bl[4];
            ldsm4t(bh, wkH + tp * 32);
            ldsm4t(bl, wkL + tp * 32);
            mmabf(acc[2 * tp], ah, bh);
            mmabf(acc[2 * tp], ah, bl);
            mmabf(acc[2 * tp], al, bh);
            mmabf(acc[2 * tp + 1], ah, bh + 2);
            mmabf(acc[2 * tp + 1], ah, bl + 2);
            mmabf(acc[2 * tp + 1], al, bh + 2);
        }
        if (NT & 1) {
            uint32_t bh[2], bl[2];
            ldsm2t(bh, wkH + (NT - 1) * 16);
            ldsm2t(bl, wkL + (NT - 1) * 16);
            mmabf(acc[NT - 1], ah, bh);
            mmabf(acc[NT - 1], ah, bl);
            mmabf(acc[NT - 1], al, bh);
        }
    }
}

__global__ __launch_bounds__(THREADS, 2) void main_kernel(
    const float* __restrict__ ctxv, const float* __restrict__ ext,
    const float* __restrict__ qvs, const float* __restrict__ qc,
    const float* __restrict__ b00, const float* __restrict__ b01,
    const float* __restrict__ b02, const float* __restrict__ b10,
    const float* __restrict__ b11, const float* __restrict__ b12,
    const float* __restrict__ pb,
    float* __restrict__ out) {
    extern __shared__ char smc[];
    int* rowBase = (int*)(smc + SM_RB);
    float* w8S   = (float*)(smc + SM_W8);
    float* ptQ   = (float*)(smc + SM_PTQ);
    float* ptR   = (float*)(smc + SM_PTR);
    float* ptT   = (float*)(smc + SM_PTT);
    int* nearS   = (int*)(smc + SM_NEAR);
    float* qvS   = (float*)(smc + SM_MISC);
    float* voxS  = qvS + 3;
    float* minS  = voxS + 3;

    const int tid = threadIdx.x;
    const int lane = tid & 31;
    const int warp = tid >> 5;
    const int mw = warp >> 1;      // 0..3: 16-row slice
    const int nw = warp & 1;       // 0..1: N half
    const int pbase = blockIdx.x * PTSB;
    const uint32_t smb = (uint32_t)__cvta_generic_to_shared(smc);

    const int r0 = mw * 16 + (lane >> 2);
    const int r1 = r0 + 8;
    const int cb = (lane & 3) * 2;
    uint32_t* ahp = (uint32_t*)(smc + SM_AH);
    uint32_t* alp = (uint32_t*)(smc + SM_AL);

    // Kick off round-0 weight staging immediately (overlaps feature setup).
    cpw(0, 160, smb, tid);

    // ---- feature setup ----
    if (tid < 3) {
        float o = ext[tid * 32768];
        qvS[tid] = qvs[tid];
        voxS[tid] = fabsf(ext[tid * 32768 + 1057] - o);
        minS[tid] = fdec(g_min_enc[tid]);
    }
    if (tid < PTSB * 3) {
        int pt = tid / 3, d = tid - pt * 3;
        float o = ext[d * 32768];
        float v = fabsf(ext[d * 32768 + 1057] - o);
        float q = qc[d * QTOT + pbase + pt];
        int n = __float2int_rn((q - o) / v);
        nearS[tid] = min(max(n, 0), 30);
        ptQ[tid] = q;
    }
    __syncthreads();
    if (tid < PTSB * 3) {
        int pt = tid / 3, d = tid - pt * 3;
        float cc = ext[d * 32768 + nearS[pt * 3] * 1024 + nearS[pt * 3 + 1] * 32 + nearS[pt * 3 + 2]];
        float raw = cc - ptQ[tid];
        ptR[tid] = raw;
        float v = voxS[d];
        float clampc = fmaf(v, -0.5f, 1e-7f);
        float rel0 = fmaxf(raw, clampc);
        float g = fminf(fmaxf((rel0 - 0.5f) * 2.0f, -1.0f + 1e-7f), 1.0f - 1e-7f);
        ptT[tid] = (g + 1.0f) * 0.5f;
    }
    if (tid < TROWS) {
        int pt = tid >> 3, cn = tid & 7;
        int ix = nearS[pt * 3 + 0] + ((cn >> 2) & 1);
        int iy = nearS[pt * 3 + 1] + ((cn >> 1) & 1);
        int iz = nearS[pt * 3 + 2] + (cn & 1);
        rowBase[tid] = ix * 1024 + iy * 32 + iz;
    }
    __syncthreads();

    // ---- trilinear weights + coord features (one thread per row) ----
    if (tid < TROWS) {
        int row = tid;
        int pt = row >> 3, cn = row & 7;
        float wi = ((cn >> 2) & 1) ? ptT[pt * 3 + 2] : 1.0f - ptT[pt * 3 + 2];
        float wj = ((cn >> 1) & 1) ? ptT[pt * 3 + 1] : 1.0f - ptT[pt * 3 + 1];
        float wk = (cn & 1) ? ptT[pt * 3 + 0] : 1.0f - ptT[pt * 3 + 0];
        w8S[row] = wi * wj * wk;

        float f[64];
        f[60] = f[61] = f[62] = f[63] = 0.f;
        int rb = rowBase[row];
#pragma unroll
        for (int d = 0; d < 3; d++) {
            int off = (d == 0) ? ((cn >> 2) & 1) : (d == 1) ? ((cn >> 1) & 1) : (cn & 1);
            float v = voxS[d];
            float clampc = fmaf(v, -0.5f, 1e-7f);
            float raw = ptR[pt * 3 + d] + (float)off * v;
            float rel = fmaxf(raw, clampc);
            float rmin = fmaxf(minS[d] + (float)off * v, clampc);
            float rn = (rel - rmin) / (1.5f * v);
            f[d] = qvS[d];
            f[3 + d] = ext[d * 32768 + rb];
            f[6 + d] = ptQ[pt * 3 + d];
            f[9 + d] = rn;
            const float TWO_PI = 6.2831853071795864769f;
#pragma unroll
            for (int i = 0; i < 8; i++) {
                float fr = exp2f((float)i * 0.29024101186092026f);  // 5^(i/8)
                float ang = TWO_PI * rn * fr;
                f[12 + d * 16 + i] = __sinf(ang);
                f[12 + d * 16 + 8 + i] = __cosf(ang);
            }
        }
        int base = row * ASTR;
        for (int c = 0; c < 64; c += 2) {
            uint32_t hw, lw; split2(f[c], f[c + 1], hw, lw);
            ahp[(base + 96 + c) >> 1] = hw;
            alp[(base + 96 + c) >> 1] = lw;
        }
    }

    // ---- skip-state x lives in registers (fragment-mapped) + fill A x-cols ----
    float xreg[6][4];
    {
        int rb0 = rowBase[r0], rb1 = rowBase[r1];
#pragma unroll
        for (int t = 0; t < 6; t++) {
            int c = (nw * 6 + t) * 8 + cb;
            xreg[t][0] = __ldg(ctxv + c * 32768 + rb0);
            xreg[t][1] = __ldg(ctxv + (c + 1) * 32768 + rb0);
            xreg[t][2] = __ldg(ctxv + c * 32768 + rb1);
            xreg[t][3] = __ldg(ctxv + (c + 1) * 32768 + rb1);
            uint32_t hw, lw;
            split2(xreg[t][0], xreg[t][1], hw, lw);
            ahp[(r0 * ASTR + c) >> 1] = hw;
            alp[(r0 * ASTR + c) >> 1] = lw;
            split2(xreg[t][2], xreg[t][3], hw, lw);
            ahp[(r1 * ASTR + c) >> 1] = hw;
            alp[(r1 * ASTR + c) >> 1] = lw;
        }
    }

    // ldmatrix base addresses (bytes)
    const uint32_t aH = smb + SM_AH + ((mw * 16 + (lane & 15)) * ASTR + (lane >> 4) * 8) * 2;
    const uint32_t aL = aH + (SM_AL - SM_AH);
    const uint32_t wHb = smb + SM_WH + (((lane & 15)) * WSTR + (lane >> 4) * 8) * 2;
    const uint32_t wLb = wHb + (SM_WL - SM_WH);

    // ---- 7 rounds: L0, L1, L2, L0', L1', L2', post ----
    const float* Bt[7] = {b00, b01, b02, b10, b11, b12, pb};
    const int Kpad[7]  = {160, 96, 96, 160, 96, 96, 96};

#pragma unroll 1
    for (int r = 0; r < 7; r++) {
        CP_WAIT0();
        __syncthreads();   // W[r] + prev-round A writes visible everywhere

        if (r < 6) {
            float acc[6][4];
#pragma unroll
            for (int t = 0; t < 6; t++)
                acc[t][0] = acc[t][1] = acc[t][2] = acc[t][3] = 0.0f;
            do_round<6>(acc, Kpad[r] >> 4, aH, aL, wHb + nw * 96, wLb + nw * 96);

            __syncthreads();   // all W[r] reads + A reads done
            cpw(r + 1, Kpad[r + 1], smb, tid);   // copy flies during epilogue

            bool skip = (r % 3 == 2);
            const float* bias = Bt[r];
#pragma unroll
            for (int t = 0; t < 6; t++) {
                int c = (nw * 6 + t) * 8 + cb;
                float b0 = __ldg(bias + c), b1 = __ldg(bias + c + 1);
                float a0 = silu(acc[t][0] + b0), a1 = silu(acc[t][1] + b1);
                float a2 = silu(acc[t][2] + b0), a3 = silu(acc[t][3] + b1);
                if (skip) {
                    a0 += xreg[t][0]; a1 += xreg[t][1];
                    a2 += xreg[t][2]; a3 += xreg[t][3];
                    xreg[t][0] = a0; xreg[t][1] = a1;
                    xreg[t][2] = a2; xreg[t][3] = a3;
                }
                uint32_t hw, lw;
                split2(a0, a1, hw, lw);
                ahp[(r0 * ASTR + c) >> 1] = hw;
                alp[(r0 * ASTR + c) >> 1] = lw;
                split2(a2, a3, hw, lw);
                ahp[(r1 * ASTR + c) >> 1] = hw;
                alp[(r1 * ASTR + c) >> 1] = lw;
            }
        } else {
            float acc[3][4];
#pragma unroll
            for (int t = 0; t < 3; t++)
                acc[t][0] = acc[t][1] = acc[t][2] = acc[t][3] = 0.0f;
            do_round<3>(acc, 6, aH, aL, wHb + nw * 48, wLb + nw * 48);

            float w8a = w8S[r0], w8b = w8S[r1];
            int ptA = mw * 2, ptB = mw * 2 + 1;
#pragma unroll
            for (int t = 0; t < 3; t++) {
                int c = (nw * 3 + t) * 8 + cb;
                float b0 = (c < OUTC) ? __ldg(pb + c) : 0.0f;
                float b1 = (c + 1 < OUTC) ? __ldg(pb + c + 1) : 0.0f;
                float v0 = (acc[t][0] + b0) * w8a;
                float v1 = (acc[t][1] + b1) * w8a;
                float v2 = (acc[t][2] + b0) * w8b;
                float v3 = (acc[t][3] + b1) * w8b;
#pragma unroll
                for (int m = 4; m <= 16; m <<= 1) {
                    v0 += __shfl_xor_sync(0xffffffffu, v0, m);
                    v1 += __shfl_xor_sync(0xffffffffu, v1, m);
                    v2 += __shfl_xor_sync(0xffffffffu, v2, m);
                    v3 += __shfl_xor_sync(0xffffffffu, v3, m);
                }
                if ((lane >> 2) == 0) {
                    if (c < OUTC) {
                        out[c * QTOT + pbase + ptA] = v0;
                        out[c * QTOT + pbase + ptB] = v2;
                    }
                    if (c + 1 < OUTC) {
                        out[(c + 1) * QTOT + pbase + ptA] = v1;
                        out[(c + 1) * QTOT + pbase + ptB] = v3;
                    }
                }
            }
        }
    }

    // Self-reset of the global-min scratch for the next graph replay.
    if (tid == 0) {
        __threadfence();
        unsigned old = atomicAdd(&g_done, 1u);
        if (old == (unsigned)(gridDim.x - 1)) {
            g_min_enc[0] = 0xFFFFFFFFu;
            g_min_enc[1] = 0xFFFFFFFFu;
            g_min_enc[2] = 0xFFFFFFFFu;
            g_done = 0;
        }
    }
}

extern "C" void kernel_launch(void* const* d_in, const int* in_sizes, int n_in,
                              void* d_out, int out_size) {
    const float* ctxv = (const float*)d_in[0];
    const float* ext  = (const float*)d_in[1];
    const float* qvs  = (const float*)d_in[2];
    const float* qc   = (const float*)d_in[3];
    const float* w00 = (const float*)d_in[4];
    const float* b00 = (const float*)d_in[5];
    const float* w01 = (const float*)d_in[6];
    const float* b01 = (const float*)d_in[7];
    const float* w02 = (const float*)d_in[8];
    const float* b02 = (const float*)d_in[9];
    const float* w10 = (const float*)d_in[10];
    const float* b10 = (const float*)d_in[11];
    const float* w11 = (const float*)d_in[12];
    const float* b11 = (const float*)d_in[13];
    const float* w12 = (const float*)d_in[14];
    const float* b12 = (const float*)d_in[15];
    const float* pw  = (const float*)d_in[16];
    const float* pb  = (const float*)d_in[17];
    float* out = (float*)d_out;

    cudaFuncSetAttribute(main_kernel, cudaFuncAttributeMaxDynamicSharedMemorySize, SMEM_TOTAL);

    min_kernel<<<QTOT / 256, 256>>>(ext, qc);
    prep_w<<<(7 * WPLANE + 255) / 256, 256>>>(w00, w01, w02, w10, w11, w12, pw);
    main_kernel<<<QTOT / PTSB, THREADS, SMEM_TOTAL>>>(
        ctxv, ext, qvs, qc,
        b00, b01, b02, b10, b11, b12, pb,
        out);
}